// round 8
// baseline (speedup 1.0000x reference)
#include <cuda_runtime.h>
#include <cuda_bf16.h>
#include <cuda_fp16.h>
#include <cstdint>

// ---------------------------------------------------------------------------
// Problem constants
// ---------------------------------------------------------------------------
#define BATCH   2
#define NTOK    4096
#define DH      256
#define DK      32
#define SCALE   0.125f
#define LOG2E   1.4426950408889634f
#define QSCALE  (SCALE * LOG2E)
#define C2OFF   12.0f

// attention tiling
#define QT      64
#define KT2     32            // keys per tile (split-KV)
#define DP      264           // padded row (16-bit elems)
#define NSPLIT  2

// ---------------------------------------------------------------------------
// Scratch
// ---------------------------------------------------------------------------
__device__ __nv_bfloat16 g_Q[(size_t)BATCH * NTOK * DH];
__device__ __nv_bfloat16 g_K[(size_t)BATCH * NTOK * DH];
__device__ __half        g_V[(size_t)BATCH * NTOK * DH];
__device__ float         g_Osp[(size_t)NSPLIT * BATCH * NTOK * DH];  // unnormalized
__device__ float         g_L[(size_t)NSPLIT * BATCH * NTOK];        // row sums

// ---------------------------------------------------------------------------
// PTX helpers
// ---------------------------------------------------------------------------
__device__ __forceinline__ void mma16816bf(float* c, const uint32_t* a, uint32_t b0, uint32_t b1) {
    asm volatile(
        "mma.sync.aligned.m16n8k16.row.col.f32.bf16.bf16.f32 "
        "{%0,%1,%2,%3}, {%4,%5,%6,%7}, {%8,%9}, {%0,%1,%2,%3};\n"
        : "+f"(c[0]), "+f"(c[1]), "+f"(c[2]), "+f"(c[3])
        : "r"(a[0]), "r"(a[1]), "r"(a[2]), "r"(a[3]), "r"(b0), "r"(b1));
}

__device__ __forceinline__ void mma16816h(float* c, const uint32_t* a, uint32_t b0, uint32_t b1) {
    asm volatile(
        "mma.sync.aligned.m16n8k16.row.col.f32.f16.f16.f32 "
        "{%0,%1,%2,%3}, {%4,%5,%6,%7}, {%8,%9}, {%0,%1,%2,%3};\n"
        : "+f"(c[0]), "+f"(c[1]), "+f"(c[2]), "+f"(c[3])
        : "r"(a[0]), "r"(a[1]), "r"(a[2]), "r"(a[3]), "r"(b0), "r"(b1));
}

__device__ __forceinline__ void mma_tf32(float* c, const uint32_t* a, uint32_t b0, uint32_t b1) {
    asm volatile(
        "mma.sync.aligned.m16n8k8.row.col.f32.tf32.tf32.f32 "
        "{%0,%1,%2,%3}, {%4,%5,%6,%7}, {%8,%9}, {%0,%1,%2,%3};\n"
        : "+f"(c[0]), "+f"(c[1]), "+f"(c[2]), "+f"(c[3])
        : "r"(a[0]), "r"(a[1]), "r"(a[2]), "r"(a[3]), "r"(b0), "r"(b1));
}

__device__ __forceinline__ uint32_t f2tf32(float f) {
    uint32_t u;
    asm("cvt.rna.tf32.f32 %0, %1;" : "=r"(u) : "f"(f));
    return u;
}

__device__ __forceinline__ void ldsm_x4(uint32_t* r, uint32_t addr) {
    asm volatile("ldmatrix.sync.aligned.m8n8.x4.shared.b16 {%0,%1,%2,%3}, [%4];"
                 : "=r"(r[0]), "=r"(r[1]), "=r"(r[2]), "=r"(r[3]) : "r"(addr));
}

__device__ __forceinline__ void ldsm_x4_t(uint32_t* r, uint32_t addr) {
    asm volatile("ldmatrix.sync.aligned.m8n8.x4.trans.shared.b16 {%0,%1,%2,%3}, [%4];"
                 : "=r"(r[0]), "=r"(r[1]), "=r"(r[2]), "=r"(r[3]) : "r"(addr));
}

__device__ __forceinline__ uint32_t pack_f16(float hi, float lo) {
    uint32_t d;
    asm("cvt.rn.f16x2.f32 %0, %1, %2;" : "=r"(d) : "f"(hi), "f"(lo));
    return d;
}
__device__ __forceinline__ uint32_t ex2_f16x2(uint32_t s) {
    uint32_t d;
    asm("ex2.approx.f16x2 %0, %1;" : "=r"(d) : "r"(s));
    return d;
}

__device__ __forceinline__ void cp_async16(uint32_t smem, const void* gptr) {
    asm volatile("cp.async.cg.shared.global [%0], [%1], 16;" :: "r"(smem), "l"(gptr));
}
#define CP_COMMIT() asm volatile("cp.async.commit_group;")
#define CP_WAIT0()  asm volatile("cp.async.wait_group 0;")

// ===========================================================================
// Kernel 1: Q projection, tf32 tensor cores + cp.async double buffer.
//   CTA tile 64n x 64o, grid 512, 8 warps (2n x 4o), warp tile 32n x 16o.
// ===========================================================================
__global__ void __launch_bounds__(256) qproj_kernel(
    const float* __restrict__ F, const float* __restrict__ Wq, const float* __restrict__ bq)
{
    const int b  = blockIdx.z;
    const int n0 = blockIdx.x * 64;
    const int o0 = blockIdx.y * 64;
    const int tid = threadIdx.x, warp = tid >> 5, lane = tid & 31;
    const int warp_n = warp & 1, warp_o = warp >> 1;
    const int g = lane >> 2, lk = lane & 3;

    __shared__ float As[2][16][72];   // [stage][c][n]
    __shared__ float Ws[2][64][20];   // [stage][o][c]

    const uint32_t as_b = (uint32_t)__cvta_generic_to_shared(&As[0][0][0]);
    const uint32_t ws_b = (uint32_t)__cvta_generic_to_shared(&Ws[0][0][0]);

    float acc[2][2][4];
#pragma unroll
    for (int mb = 0; mb < 2; mb++)
#pragma unroll
        for (int ob = 0; ob < 2; ob++)
#pragma unroll
            for (int i = 0; i < 4; i++) acc[mb][ob][i] = 0.f;

    const float* Fb = F + (size_t)b * DH * NTOK;

    auto stage_in = [&](int kt, int s) {
        int c0 = kt * 16;
        {   // As: 16c x 64n = 256 chunks, 1/thread
            int cc = tid >> 4, ch = (tid & 15) * 4;
            cp_async16(as_b + (uint32_t)((s * 16 + cc) * 72 + ch) * 4,
                       &Fb[(size_t)(c0 + cc) * NTOK + n0 + ch]);
        }
        {   // Ws: 64o x 16c = 256 chunks, 1/thread
            int oo = tid >> 2, ch = (tid & 3) * 4;
            cp_async16(ws_b + (uint32_t)((s * 64 + oo) * 20 + ch) * 4,
                       &Wq[(size_t)(o0 + oo) * DH + c0 + ch]);
        }
    };

    stage_in(0, 0);
    CP_COMMIT();

    for (int kt = 0; kt < 16; kt++) {
        CP_WAIT0();
        __syncthreads();
        if (kt + 1 < 16) { stage_in(kt + 1, (kt + 1) & 1); CP_COMMIT(); }
        const int s = kt & 1;

#pragma unroll
        for (int k8 = 0; k8 < 2; k8++) {
            const int kb = k8 * 8;
            uint32_t a[2][4];
#pragma unroll
            for (int mb = 0; mb < 2; mb++) {
                int rm = warp_n * 32 + mb * 16 + g;
                a[mb][0] = f2tf32(As[s][kb + lk][rm]);
                a[mb][1] = f2tf32(As[s][kb + lk][rm + 8]);
                a[mb][2] = f2tf32(As[s][kb + 4 + lk][rm]);
                a[mb][3] = f2tf32(As[s][kb + 4 + lk][rm + 8]);
            }
#pragma unroll
            for (int ob = 0; ob < 2; ob++) {
                int oc = warp_o * 16 + ob * 8 + g;
                uint32_t b0 = f2tf32(Ws[s][oc][kb + lk]);
                uint32_t b1 = f2tf32(Ws[s][oc][kb + 4 + lk]);
                mma_tf32(acc[0][ob], a[0], b0, b1);
                mma_tf32(acc[1][ob], a[1], b0, b1);
            }
        }
        __syncthreads();
    }

#pragma unroll
    for (int ob = 0; ob < 2; ob++) {
        int o = o0 + warp_o * 16 + ob * 8 + 2 * lk;
        float bv0 = bq[o], bv1 = bq[o + 1];
#pragma unroll
        for (int mb = 0; mb < 2; mb++) {
            int r = n0 + warp_n * 32 + mb * 16 + g;
            __nv_bfloat162 lo = __floats2bfloat162_rn(
                (acc[mb][ob][0] + bv0) * QSCALE, (acc[mb][ob][1] + bv1) * QSCALE);
            __nv_bfloat162 hi = __floats2bfloat162_rn(
                (acc[mb][ob][2] + bv0) * QSCALE, (acc[mb][ob][3] + bv1) * QSCALE);
            *reinterpret_cast<uint32_t*>(&g_Q[((size_t)b * NTOK + r) * DH + o]) =
                *reinterpret_cast<uint32_t*>(&lo);
            *reinterpret_cast<uint32_t*>(&g_Q[((size_t)b * NTOK + r + 8) * DH + o]) =
                *reinterpret_cast<uint32_t*>(&hi);
        }
    }
}

// ===========================================================================
// Kernel 2: K (bf16) and V (f16) projection, weights register-resident.
// ===========================================================================
__global__ void __launch_bounds__(256) kvproj_kernel(
    const float* __restrict__ FK,
    const float* __restrict__ Wk, const float* __restrict__ bk,
    const float* __restrict__ Wv, const float* __restrict__ bv)
{
    const bool isK = (blockIdx.y == 0);
    const float* W    = isK ? Wk : Wv;
    const float* bias = isK ? bk : bv;

    const int t0 = blockIdx.x * 64;
    const int b  = t0 >> 12;
    const int n0 = t0 & (NTOK - 1);
    const int o  = threadIdx.x;

    __shared__ float xs[64][36];

    float w[32];
#pragma unroll
    for (int i = 0; i < 8; i++) {
        float4 v = *reinterpret_cast<const float4*>(&W[(size_t)o * DK + i * 4]);
        w[i * 4 + 0] = v.x; w[i * 4 + 1] = v.y; w[i * 4 + 2] = v.z; w[i * 4 + 3] = v.w;
    }
    const float bb = bias[o];

    const float* FKb = FK + (size_t)b * DK * NTOK;
#pragma unroll
    for (int p = 0; p < 2; p++) {
        int idx = threadIdx.x + p * 256;
        int c = idx >> 4, t4 = (idx & 15) * 4;
        float4 v = *reinterpret_cast<const float4*>(&FKb[(size_t)c * NTOK + n0 + t4]);
        xs[t4 + 0][c] = v.x; xs[t4 + 1][c] = v.y; xs[t4 + 2][c] = v.z; xs[t4 + 3][c] = v.w;
    }
    __syncthreads();

    for (int tok = 0; tok < 64; tok++) {
        float acc = bb;
#pragma unroll
        for (int i = 0; i < 8; i++) {
            float4 x = *reinterpret_cast<float4*>(&xs[tok][i * 4]);
            acc += x.x * w[i * 4 + 0] + x.y * w[i * 4 + 1]
                 + x.z * w[i * 4 + 2] + x.w * w[i * 4 + 3];
        }
        size_t di = ((size_t)b * NTOK + n0 + tok) * DH + o;
        if (isK) g_K[di] = __float2bfloat16(acc);
        else     g_V[di] = __float2half(acc);
    }
}

// ===========================================================================
// Kernel 3: flash attention, split-KV, Q fragments register-resident.
//   (unchanged from the 176.1us passing version)
// ===========================================================================
__global__ void __launch_bounds__(128) attn_kernel()
{
    extern __shared__ __align__(16) __nv_bfloat16 sm[];
    __nv_bfloat16* Qs = sm;

    const int b     = blockIdx.y;
    const int split = blockIdx.z;
    const int q0    = blockIdx.x * QT;
    const int tid = threadIdx.x, warp = tid >> 5, lane = tid & 31;

    const int kglob0 = split * (NTOK / NSPLIT);

    const __nv_bfloat16* Qg = g_Q + ((size_t)b * NTOK + q0) * DH;
    const __nv_bfloat16* Kg = g_K + (size_t)b * NTOK * DH;
    const __half*        Vg = g_V + (size_t)b * NTOK * DH;

    const uint32_t smb = (uint32_t)__cvta_generic_to_shared(sm);

    const int qrow = warp * 16 + (lane & 15);
    const int qcol = (lane >> 4) * 8;
    const uint32_t qaddr = smb + (uint32_t)(qrow * DP + qcol) * 2;
    const int krow = (lane & 7) + ((lane >> 4) << 3);
    const int kcol = ((lane >> 3) & 1) * 8;
    const int vrow = lane & 15;
    const int vcol = (lane >> 4) * 8;

    auto kbase = [&](int s) -> uint32_t { return smb + (uint32_t)(QT + s * 2 * KT2) * DP * 2; };

    auto prefetch = [&](int k0, int s) {
        uint32_t kb = kbase(s);
        uint32_t vb = kb + KT2 * DP * 2;
#pragma unroll
        for (int i = 0; i < 8; i++) {
            int idx = tid + i * 128;
            int r = idx >> 5, c = (idx & 31) * 8;
            uint32_t so = (uint32_t)(r * DP + c) * 2;
            cp_async16(kb + so, Kg + (size_t)(k0 + r) * DH + c);
            cp_async16(vb + so, Vg + (size_t)(k0 + r) * DH + c);
        }
    };

    prefetch(kglob0, 0);
    CP_COMMIT();

    for (int idx = tid; idx < QT * 32; idx += 128) {
        int r = idx >> 5, c = (idx & 31) * 8;
        *reinterpret_cast<uint4*>(Qs + r * DP + c) =
            *reinterpret_cast<const uint4*>(Qg + (size_t)r * DH + c);
    }
    __syncthreads();

    uint32_t qf[16][4];
#pragma unroll
    for (int d0 = 0; d0 < 16; d0++)
        ldsm_x4(qf[d0], qaddr + (uint32_t)(d0 * 16) * 2);

    float acc[32][4];
#pragma unroll
    for (int i = 0; i < 32; i++)
#pragma unroll
        for (int j = 0; j < 4; j++) acc[i][j] = 0.f;
    float lsum[4] = {0.f, 0.f, 0.f, 0.f};
    const uint32_t ONES = 0x3C003C00u;

    const int NT = (NTOK / NSPLIT) / KT2;   // 64
    for (int t = 0; t < NT; t++) {
        CP_WAIT0();
        __syncthreads();
        if (t + 1 < NT) { prefetch(kglob0 + (t + 1) * KT2, (t + 1) & 1); CP_COMMIT(); }

        const uint32_t ksa = kbase(t & 1);
        const uint32_t vsa = ksa + KT2 * DP * 2;

        float S[4][4];
#pragma unroll
        for (int j = 0; j < 4; j++)
#pragma unroll
            for (int i = 0; i < 4; i++) S[j][i] = -C2OFF;

#pragma unroll
        for (int d0 = 0; d0 < 16; d0++) {
#pragma unroll
            for (int j = 0; j < 4; j += 2) {
                uint32_t bk4[4];
                ldsm_x4(bk4, ksa + (uint32_t)((j * 8 + krow) * DP + d0 * 16 + kcol) * 2);
                mma16816bf(S[j],     qf[d0], bk4[0], bk4[1]);
                mma16816bf(S[j + 1], qf[d0], bk4[2], bk4[3]);
            }
        }

        uint32_t Pa[2][4];
#pragma unroll
        for (int j = 0; j < 4; j++) {
            uint32_t p01 = ex2_f16x2(pack_f16(S[j][1], S[j][0]));
            uint32_t p23 = ex2_f16x2(pack_f16(S[j][3], S[j][2]));
            int kk = j >> 1;
            if ((j & 1) == 0) { Pa[kk][0] = p01; Pa[kk][1] = p23; }
            else              { Pa[kk][2] = p01; Pa[kk][3] = p23; }
        }

#pragma unroll
        for (int kk = 0; kk < 2; kk++) mma16816h(lsum, Pa[kk], ONES, ONES);

#pragma unroll
        for (int dt = 0; dt < 32; dt += 2) {
#pragma unroll
            for (int kk = 0; kk < 2; kk++) {
                uint32_t bv4[4];
                ldsm_x4_t(bv4, vsa + (uint32_t)((kk * 16 + vrow) * DP + dt * 8 + vcol) * 2);
                mma16816h(acc[dt],     Pa[kk], bv4[0], bv4[1]);
                mma16816h(acc[dt + 1], Pa[kk], bv4[2], bv4[3]);
            }
        }
    }

    float* Ob = g_Osp + ((size_t)split * BATCH + b) * NTOK * DH;
    const int r0 = q0 + warp * 16 + (lane >> 2);
    const int r1 = r0 + 8;
    const int dcol = (lane & 3) * 2;
#pragma unroll
    for (int dt = 0; dt < 32; dt++) {
        int d = dt * 8 + dcol;
        *reinterpret_cast<float2*>(Ob + (size_t)r0 * DH + d) =
            make_float2(acc[dt][0], acc[dt][1]);
        *reinterpret_cast<float2*>(Ob + (size_t)r1 * DH + d) =
            make_float2(acc[dt][2], acc[dt][3]);
    }
    if ((lane & 3) == 0) {
        g_L[((size_t)split * BATCH + b) * NTOK + r0] = lsum[0];
        g_L[((size_t)split * BATCH + b) * NTOK + r1] = lsum[2];
    }
}

// ===========================================================================
// Kernel 4: output projection + residual, merge fused.
//   CTA tile 64c x 64n, grid 512, 8 warps (2c x 4n), warp tile 32c x 16n.
// ===========================================================================
__global__ void __launch_bounds__(256) oproj_kernel(
    const float* __restrict__ Wo, const float* __restrict__ bo,
    const float* __restrict__ F, float* __restrict__ out)
{
    const int b  = blockIdx.z;
    const int n0 = blockIdx.x * 64;
    const int c0 = blockIdx.y * 64;
    const int tid = threadIdx.x, warp = tid >> 5, lane = tid & 31;
    const int warp_c = warp & 1, warp_nn = warp >> 1;
    const int g = lane >> 2, lk = lane & 3;

    __shared__ float As[2][64][20];       // [stage][c][o]
    __shared__ float Bs[2][2][64][20];    // [stage][split][n][o]
    __shared__ float invs[64];

    const uint32_t as_b = (uint32_t)__cvta_generic_to_shared(&As[0][0][0]);
    const uint32_t bs_b = (uint32_t)__cvta_generic_to_shared(&Bs[0][0][0][0]);

    if (tid < 64) {
        int row = b * NTOK + n0 + tid;
        invs[tid] = 1.f / (g_L[row] + g_L[(size_t)BATCH * NTOK + row]);
    }

    float acc[2][2][4];
#pragma unroll
    for (int mb = 0; mb < 2; mb++)
#pragma unroll
        for (int ob = 0; ob < 2; ob++)
#pragma unroll
            for (int i = 0; i < 4; i++) acc[mb][ob][i] = 0.f;

    const float* O0 = g_Osp + (size_t)b * NTOK * DH;
    const float* O1 = g_Osp + ((size_t)BATCH + b) * NTOK * DH;

    auto stage_in = [&](int kt, int s) {
        int o0 = kt * 16;
        {   // As: 64c x 16o = 256 chunks, 1/thread
            int cc = tid >> 2, ch = (tid & 3) * 4;
            cp_async16(as_b + (uint32_t)((s * 64 + cc) * 20 + ch) * 4,
                       &Wo[(size_t)(c0 + cc) * DH + o0 + ch]);
        }
        {   // Bs: 2 splits x 256 chunks, 2/thread
            int nn = tid >> 2, ch = (tid & 3) * 4;
            size_t go = (size_t)(n0 + nn) * DH + o0 + ch;
            uint32_t so = (uint32_t)(((s * 2 + 0) * 64 + nn) * 20 + ch) * 4;
            cp_async16(bs_b + so, O0 + go);
            cp_async16(bs_b + so + 64 * 20 * 4, O1 + go);
        }
    };

    stage_in(0, 0);
    CP_COMMIT();

    for (int kt = 0; kt < 16; kt++) {
        CP_WAIT0();
        __syncthreads();
        if (kt + 1 < 16) { stage_in(kt + 1, (kt + 1) & 1); CP_COMMIT(); }
        const int s = kt & 1;

#pragma unroll
        for (int k8 = 0; k8 < 2; k8++) {
            const int kb = k8 * 8;
            uint32_t a[2][4];
#pragma unroll
            for (int mb = 0; mb < 2; mb++) {
                int rm = warp_c * 32 + mb * 16 + g;
                a[mb][0] = f2tf32(As[s][rm][kb + lk]);
                a[mb][1] = f2tf32(As[s][rm + 8][kb + lk]);
                a[mb][2] = f2tf32(As[s][rm][kb + 4 + lk]);
                a[mb][3] = f2tf32(As[s][rm + 8][kb + 4 + lk]);
            }
#pragma unroll
            for (int ob = 0; ob < 2; ob++) {
                int nc = warp_nn * 16 + ob * 8 + g;
                float inv = invs[nc];
                uint32_t b0 = f2tf32((Bs[s][0][nc][kb + lk] + Bs[s][1][nc][kb + lk]) * inv);
                uint32_t b1 = f2tf32((Bs[s][0][nc][kb + 4 + lk] + Bs[s][1][nc][kb + 4 + lk]) * inv);
                mma_tf32(acc[0][ob], a[0], b0, b1);
                mma_tf32(acc[1][ob], a[1], b0, b1);
            }
        }
        __syncthreads();
    }

#pragma unroll
    for (int mb = 0; mb < 2; mb++) {
#pragma unroll
        for (int rr = 0; rr < 2; rr++) {
            int c = c0 + warp_c * 32 + mb * 16 + g + rr * 8;
            float bias = bo[c];
#pragma unroll
            for (int ob = 0; ob < 2; ob++) {
                int n = n0 + warp_nn * 16 + ob * 8 + 2 * lk;
                size_t base = ((size_t)b * DH + c) * NTOK + n;
                float2 f = *reinterpret_cast<const float2*>(F + base);
                float2 r;
                r.x = f.x + bias + acc[mb][ob][rr * 2 + 0];
                r.y = f.y + bias + acc[mb][ob][rr * 2 + 1];
                *reinterpret_cast<float2*>(out + base) = r;
            }
        }
    }
}

// ===========================================================================
// Launch
// ===========================================================================
extern "C" void kernel_launch(void* const* d_in, const int* in_sizes, int n_in,
                              void* d_out, int out_size)
{
    const float* F  = (const float*)d_in[0];
    const float* FK = (const float*)d_in[1];
    const float* Wq = (const float*)d_in[2];
    const float* bq = (const float*)d_in[3];
    const float* Wk = (const float*)d_in[4];
    const float* bk = (const float*)d_in[5];
    const float* Wv = (const float*)d_in[6];
    const float* bv = (const float*)d_in[7];
    const float* Wo = (const float*)d_in[8];
    const float* bo = (const float*)d_in[9];
    float* out = (float*)d_out;

    const int attn_smem = (QT + 2 * 2 * KT2) * DP * 2;   // 101,376 bytes
    cudaFuncSetAttribute(attn_kernel, cudaFuncAttributeMaxDynamicSharedMemorySize, attn_smem);

    qproj_kernel<<<dim3(NTOK / 64, DH / 64, BATCH), 256>>>(F, Wq, bq);
    kvproj_kernel<<<dim3(BATCH * NTOK / 64, 2), 256>>>(FK, Wk, bk, Wv, bv);
    attn_kernel<<<dim3(NTOK / QT, BATCH, NSPLIT), 128, attn_smem>>>();
    oproj_kernel<<<dim3(NTOK / 64, DH / 64, BATCH), 256>>>(Wo, bo, F, out);
}

// round 9
// speedup vs baseline: 1.0119x; 1.0119x over previous
#include <cuda_runtime.h>
#include <cuda_bf16.h>
#include <cuda_fp16.h>
#include <cstdint>

// ---------------------------------------------------------------------------
// Problem constants
// ---------------------------------------------------------------------------
#define BATCH   2
#define NTOK    4096
#define DH      256
#define DK      32
#define SCALE   0.125f
#define LOG2E   1.4426950408889634f
#define QSCALE  (SCALE * LOG2E)
#define C2OFF   12.0f

// attention tiling
#define QT      64
#define KT2     32
#define DP      264
#define NSPLIT  2

// ---------------------------------------------------------------------------
// Scratch
// ---------------------------------------------------------------------------
__device__ __nv_bfloat16 g_Q[(size_t)BATCH * NTOK * DH];
__device__ __nv_bfloat16 g_K[(size_t)BATCH * NTOK * DH];
__device__ __half        g_V[(size_t)BATCH * NTOK * DH];
__device__ float         g_Osp[(size_t)NSPLIT * BATCH * NTOK * DH];
__device__ float         g_L[(size_t)NSPLIT * BATCH * NTOK];

// ---------------------------------------------------------------------------
// PTX helpers
// ---------------------------------------------------------------------------
__device__ __forceinline__ void mma16816bf(float* c, const uint32_t* a, uint32_t b0, uint32_t b1) {
    asm volatile(
        "mma.sync.aligned.m16n8k16.row.col.f32.bf16.bf16.f32 "
        "{%0,%1,%2,%3}, {%4,%5,%6,%7}, {%8,%9}, {%0,%1,%2,%3};\n"
        : "+f"(c[0]), "+f"(c[1]), "+f"(c[2]), "+f"(c[3])
        : "r"(a[0]), "r"(a[1]), "r"(a[2]), "r"(a[3]), "r"(b0), "r"(b1));
}

__device__ __forceinline__ void mma16816h(float* c, const uint32_t* a, uint32_t b0, uint32_t b1) {
    asm volatile(
        "mma.sync.aligned.m16n8k16.row.col.f32.f16.f16.f32 "
        "{%0,%1,%2,%3}, {%4,%5,%6,%7}, {%8,%9}, {%0,%1,%2,%3};\n"
        : "+f"(c[0]), "+f"(c[1]), "+f"(c[2]), "+f"(c[3])
        : "r"(a[0]), "r"(a[1]), "r"(a[2]), "r"(a[3]), "r"(b0), "r"(b1));
}

__device__ __forceinline__ void mma_tf32(float* c, const uint32_t* a, uint32_t b0, uint32_t b1) {
    asm volatile(
        "mma.sync.aligned.m16n8k8.row.col.f32.tf32.tf32.f32 "
        "{%0,%1,%2,%3}, {%4,%5,%6,%7}, {%8,%9}, {%0,%1,%2,%3};\n"
        : "+f"(c[0]), "+f"(c[1]), "+f"(c[2]), "+f"(c[3])
        : "r"(a[0]), "r"(a[1]), "r"(a[2]), "r"(a[3]), "r"(b0), "r"(b1));
}

__device__ __forceinline__ uint32_t f2tf32(float f) {
    uint32_t u;
    asm("cvt.rna.tf32.f32 %0, %1;" : "=r"(u) : "f"(f));
    return u;
}

__device__ __forceinline__ void ldsm_x4(uint32_t* r, uint32_t addr) {
    asm volatile("ldmatrix.sync.aligned.m8n8.x4.shared.b16 {%0,%1,%2,%3}, [%4];"
                 : "=r"(r[0]), "=r"(r[1]), "=r"(r[2]), "=r"(r[3]) : "r"(addr));
}

__device__ __forceinline__ void ldsm_x4_t(uint32_t* r, uint32_t addr) {
    asm volatile("ldmatrix.sync.aligned.m8n8.x4.trans.shared.b16 {%0,%1,%2,%3}, [%4];"
                 : "=r"(r[0]), "=r"(r[1]), "=r"(r[2]), "=r"(r[3]) : "r"(addr));
}

__device__ __forceinline__ uint32_t pack_f16(float hi, float lo) {
    uint32_t d;
    asm("cvt.rn.f16x2.f32 %0, %1, %2;" : "=r"(d) : "f"(hi), "f"(lo));
    return d;
}
__device__ __forceinline__ uint32_t ex2_f16x2(uint32_t s) {
    uint32_t d;
    asm("ex2.approx.f16x2 %0, %1;" : "=r"(d) : "r"(s));
    return d;
}

__device__ __forceinline__ void cp_async16(uint32_t smem, const void* gptr) {
    asm volatile("cp.async.cg.shared.global [%0], [%1], 16;" :: "r"(smem), "l"(gptr));
}
#define CP_COMMIT() asm volatile("cp.async.commit_group;")
#define CP_WAIT0()  asm volatile("cp.async.wait_group 0;")

// ===========================================================================
// Kernel 1: Q projection, tf32 + 64-wide k stages (4 iterations, 8 barriers).
//   CTA tile 64n x 64o, grid 512, 8 warps (2n x 4o), warp tile 32n x 16o.
// ===========================================================================
__global__ void __launch_bounds__(256) qproj_kernel(
    const float* __restrict__ F, const float* __restrict__ Wq, const float* __restrict__ bq)
{
    const int b  = blockIdx.z;
    const int n0 = blockIdx.x * 64;
    const int o0 = blockIdx.y * 64;
    const int tid = threadIdx.x, warp = tid >> 5, lane = tid & 31;
    const int warp_n = warp & 1, warp_o = warp >> 1;
    const int g = lane >> 2, lk = lane & 3;

    __shared__ float As[2][64][72];   // [stage][c][n]  (72%32=8: lk*8+g distinct)
    __shared__ float Ws[2][64][68];   // [stage][o][c]  (68%32=4: g*4+lk distinct)

    const uint32_t as_b = (uint32_t)__cvta_generic_to_shared(&As[0][0][0]);
    const uint32_t ws_b = (uint32_t)__cvta_generic_to_shared(&Ws[0][0][0]);

    float acc[2][2][4];
#pragma unroll
    for (int mb = 0; mb < 2; mb++)
#pragma unroll
        for (int ob = 0; ob < 2; ob++)
#pragma unroll
            for (int i = 0; i < 4; i++) acc[mb][ob][i] = 0.f;

    const float* Fb = F + (size_t)b * DH * NTOK;

    auto stage_in = [&](int kt, int s) {
        int c0 = kt * 64;
#pragma unroll
        for (int p = 0; p < 4; p++) {   // As: 64c x 64n = 1024 chunks
            int idx = tid + p * 256;
            int cc = idx >> 4, ch = (idx & 15) * 4;
            cp_async16(as_b + (uint32_t)((s * 64 + cc) * 72 + ch) * 4,
                       &Fb[(size_t)(c0 + cc) * NTOK + n0 + ch]);
        }
#pragma unroll
        for (int p = 0; p < 4; p++) {   // Ws: 64o x 64c = 1024 chunks
            int idx = tid + p * 256;
            int oo = idx >> 4, ch = (idx & 15) * 4;
            cp_async16(ws_b + (uint32_t)((s * 64 + oo) * 68 + ch) * 4,
                       &Wq[(size_t)(o0 + oo) * DH + c0 + ch]);
        }
    };

    stage_in(0, 0);
    CP_COMMIT();

    for (int kt = 0; kt < 4; kt++) {
        CP_WAIT0();
        __syncthreads();
        if (kt + 1 < 4) { stage_in(kt + 1, (kt + 1) & 1); CP_COMMIT(); }
        const int s = kt & 1;

#pragma unroll
        for (int k8 = 0; k8 < 8; k8++) {
            const int kb = k8 * 8;
            uint32_t a[2][4];
#pragma unroll
            for (int mb = 0; mb < 2; mb++) {
                int rm = warp_n * 32 + mb * 16 + g;
                a[mb][0] = f2tf32(As[s][kb + lk][rm]);
                a[mb][1] = f2tf32(As[s][kb + lk][rm + 8]);
                a[mb][2] = f2tf32(As[s][kb + 4 + lk][rm]);
                a[mb][3] = f2tf32(As[s][kb + 4 + lk][rm + 8]);
            }
#pragma unroll
            for (int ob = 0; ob < 2; ob++) {
                int oc = warp_o * 16 + ob * 8 + g;
                uint32_t b0 = f2tf32(Ws[s][oc][kb + lk]);
                uint32_t b1 = f2tf32(Ws[s][oc][kb + 4 + lk]);
                mma_tf32(acc[0][ob], a[0], b0, b1);
                mma_tf32(acc[1][ob], a[1], b0, b1);
            }
        }
        __syncthreads();
    }

#pragma unroll
    for (int ob = 0; ob < 2; ob++) {
        int o = o0 + warp_o * 16 + ob * 8 + 2 * lk;
        float bv0 = bq[o], bv1 = bq[o + 1];
#pragma unroll
        for (int mb = 0; mb < 2; mb++) {
            int r = n0 + warp_n * 32 + mb * 16 + g;
            __nv_bfloat162 lo = __floats2bfloat162_rn(
                (acc[mb][ob][0] + bv0) * QSCALE, (acc[mb][ob][1] + bv1) * QSCALE);
            __nv_bfloat162 hi = __floats2bfloat162_rn(
                (acc[mb][ob][2] + bv0) * QSCALE, (acc[mb][ob][3] + bv1) * QSCALE);
            *reinterpret_cast<uint32_t*>(&g_Q[((size_t)b * NTOK + r) * DH + o]) =
                *reinterpret_cast<uint32_t*>(&lo);
            *reinterpret_cast<uint32_t*>(&g_Q[((size_t)b * NTOK + r + 8) * DH + o]) =
                *reinterpret_cast<uint32_t*>(&hi);
        }
    }
}

// ===========================================================================
// Kernel 2: K (bf16) and V (f16) projection, weights register-resident.
// ===========================================================================
__global__ void __launch_bounds__(256) kvproj_kernel(
    const float* __restrict__ FK,
    const float* __restrict__ Wk, const float* __restrict__ bk,
    const float* __restrict__ Wv, const float* __restrict__ bv)
{
    const bool isK = (blockIdx.y == 0);
    const float* W    = isK ? Wk : Wv;
    const float* bias = isK ? bk : bv;

    const int t0 = blockIdx.x * 64;
    const int b  = t0 >> 12;
    const int n0 = t0 & (NTOK - 1);
    const int o  = threadIdx.x;

    __shared__ float xs[64][36];

    float w[32];
#pragma unroll
    for (int i = 0; i < 8; i++) {
        float4 v = *reinterpret_cast<const float4*>(&W[(size_t)o * DK + i * 4]);
        w[i * 4 + 0] = v.x; w[i * 4 + 1] = v.y; w[i * 4 + 2] = v.z; w[i * 4 + 3] = v.w;
    }
    const float bb = bias[o];

    const float* FKb = FK + (size_t)b * DK * NTOK;
#pragma unroll
    for (int p = 0; p < 2; p++) {
        int idx = threadIdx.x + p * 256;
        int c = idx >> 4, t4 = (idx & 15) * 4;
        float4 v = *reinterpret_cast<const float4*>(&FKb[(size_t)c * NTOK + n0 + t4]);
        xs[t4 + 0][c] = v.x; xs[t4 + 1][c] = v.y; xs[t4 + 2][c] = v.z; xs[t4 + 3][c] = v.w;
    }
    __syncthreads();

    for (int tok = 0; tok < 64; tok++) {
        float acc = bb;
#pragma unroll
        for (int i = 0; i < 8; i++) {
            float4 x = *reinterpret_cast<float4*>(&xs[tok][i * 4]);
            acc += x.x * w[i * 4 + 0] + x.y * w[i * 4 + 1]
                 + x.z * w[i * 4 + 2] + x.w * w[i * 4 + 3];
        }
        size_t di = ((size_t)b * NTOK + n0 + tok) * DH + o;
        if (isK) g_K[di] = __float2bfloat16(acc);
        else     g_V[di] = __float2half(acc);
    }
}

// ===========================================================================
// Kernel 3: flash attention, split-KV, Q fragments register-resident.
//   (frozen: 176.1us passing version)
// ===========================================================================
__global__ void __launch_bounds__(128) attn_kernel()
{
    extern __shared__ __align__(16) __nv_bfloat16 sm[];
    __nv_bfloat16* Qs = sm;

    const int b     = blockIdx.y;
    const int split = blockIdx.z;
    const int q0    = blockIdx.x * QT;
    const int tid = threadIdx.x, warp = tid >> 5, lane = tid & 31;

    const int kglob0 = split * (NTOK / NSPLIT);

    const __nv_bfloat16* Qg = g_Q + ((size_t)b * NTOK + q0) * DH;
    const __nv_bfloat16* Kg = g_K + (size_t)b * NTOK * DH;
    const __half*        Vg = g_V + (size_t)b * NTOK * DH;

    const uint32_t smb = (uint32_t)__cvta_generic_to_shared(sm);

    const int qrow = warp * 16 + (lane & 15);
    const int qcol = (lane >> 4) * 8;
    const uint32_t qaddr = smb + (uint32_t)(qrow * DP + qcol) * 2;
    const int krow = (lane & 7) + ((lane >> 4) << 3);
    const int kcol = ((lane >> 3) & 1) * 8;
    const int vrow = lane & 15;
    const int vcol = (lane >> 4) * 8;

    auto kbase = [&](int s) -> uint32_t { return smb + (uint32_t)(QT + s * 2 * KT2) * DP * 2; };

    auto prefetch = [&](int k0, int s) {
        uint32_t kb = kbase(s);
        uint32_t vb = kb + KT2 * DP * 2;
#pragma unroll
        for (int i = 0; i < 8; i++) {
            int idx = tid + i * 128;
            int r = idx >> 5, c = (idx & 31) * 8;
            uint32_t so = (uint32_t)(r * DP + c) * 2;
            cp_async16(kb + so, Kg + (size_t)(k0 + r) * DH + c);
            cp_async16(vb + so, Vg + (size_t)(k0 + r) * DH + c);
        }
    };

    prefetch(kglob0, 0);
    CP_COMMIT();

    for (int idx = tid; idx < QT * 32; idx += 128) {
        int r = idx >> 5, c = (idx & 31) * 8;
        *reinterpret_cast<uint4*>(Qs + r * DP + c) =
            *reinterpret_cast<const uint4*>(Qg + (size_t)r * DH + c);
    }
    __syncthreads();

    uint32_t qf[16][4];
#pragma unroll
    for (int d0 = 0; d0 < 16; d0++)
        ldsm_x4(qf[d0], qaddr + (uint32_t)(d0 * 16) * 2);

    float acc[32][4];
#pragma unroll
    for (int i = 0; i < 32; i++)
#pragma unroll
        for (int j = 0; j < 4; j++) acc[i][j] = 0.f;
    float lsum[4] = {0.f, 0.f, 0.f, 0.f};
    const uint32_t ONES = 0x3C003C00u;

    const int NT = (NTOK / NSPLIT) / KT2;   // 64
    for (int t = 0; t < NT; t++) {
        CP_WAIT0();
        __syncthreads();
        if (t + 1 < NT) { prefetch(kglob0 + (t + 1) * KT2, (t + 1) & 1); CP_COMMIT(); }

        const uint32_t ksa = kbase(t & 1);
        const uint32_t vsa = ksa + KT2 * DP * 2;

        float S[4][4];
#pragma unroll
        for (int j = 0; j < 4; j++)
#pragma unroll
            for (int i = 0; i < 4; i++) S[j][i] = -C2OFF;

#pragma unroll
        for (int d0 = 0; d0 < 16; d0++) {
#pragma unroll
            for (int j = 0; j < 4; j += 2) {
                uint32_t bk4[4];
                ldsm_x4(bk4, ksa + (uint32_t)((j * 8 + krow) * DP + d0 * 16 + kcol) * 2);
                mma16816bf(S[j],     qf[d0], bk4[0], bk4[1]);
                mma16816bf(S[j + 1], qf[d0], bk4[2], bk4[3]);
            }
        }

        uint32_t Pa[2][4];
#pragma unroll
        for (int j = 0; j < 4; j++) {
            uint32_t p01 = ex2_f16x2(pack_f16(S[j][1], S[j][0]));
            uint32_t p23 = ex2_f16x2(pack_f16(S[j][3], S[j][2]));
            int kk = j >> 1;
            if ((j & 1) == 0) { Pa[kk][0] = p01; Pa[kk][1] = p23; }
            else              { Pa[kk][2] = p01; Pa[kk][3] = p23; }
        }

#pragma unroll
        for (int kk = 0; kk < 2; kk++) mma16816h(lsum, Pa[kk], ONES, ONES);

#pragma unroll
        for (int dt = 0; dt < 32; dt += 2) {
#pragma unroll
            for (int kk = 0; kk < 2; kk++) {
                uint32_t bv4[4];
                ldsm_x4_t(bv4, vsa + (uint32_t)((kk * 16 + vrow) * DP + dt * 8 + vcol) * 2);
                mma16816h(acc[dt],     Pa[kk], bv4[0], bv4[1]);
                mma16816h(acc[dt + 1], Pa[kk], bv4[2], bv4[3]);
            }
        }
    }

    float* Ob = g_Osp + ((size_t)split * BATCH + b) * NTOK * DH;
    const int r0 = q0 + warp * 16 + (lane >> 2);
    const int r1 = r0 + 8;
    const int dcol = (lane & 3) * 2;
#pragma unroll
    for (int dt = 0; dt < 32; dt++) {
        int d = dt * 8 + dcol;
        *reinterpret_cast<float2*>(Ob + (size_t)r0 * DH + d) =
            make_float2(acc[dt][0], acc[dt][1]);
        *reinterpret_cast<float2*>(Ob + (size_t)r1 * DH + d) =
            make_float2(acc[dt][2], acc[dt][3]);
    }
    if ((lane & 3) == 0) {
        g_L[((size_t)split * BATCH + b) * NTOK + r0] = lsum[0];
        g_L[((size_t)split * BATCH + b) * NTOK + r1] = lsum[2];
    }
}

// ===========================================================================
// Kernel 4: output projection + residual, merge fused.
//   CTA 64c x 64n, grid 512, 32-wide k stages (8 iterations, 16 barriers).
// ===========================================================================
__global__ void __launch_bounds__(256) oproj_kernel(
    const float* __restrict__ Wo, const float* __restrict__ bo,
    const float* __restrict__ F, float* __restrict__ out)
{
    const int b  = blockIdx.z;
    const int n0 = blockIdx.x * 64;
    const int c0 = blockIdx.y * 64;
    const int tid = threadIdx.x, warp = tid >> 5, lane = tid & 31;
    const int warp_c = warp & 1, warp_nn = warp >> 1;
    const int g = lane >> 2, lk = lane & 3;

    __shared__ float As[2][64][36];       // [stage][c][o]  (36%32=4: g*4+lk distinct)
    __shared__ float Bs[2][2][64][36];    // [stage][split][n][o]
    __shared__ float invs[64];

    const uint32_t as_b = (uint32_t)__cvta_generic_to_shared(&As[0][0][0]);
    const uint32_t bs_b = (uint32_t)__cvta_generic_to_shared(&Bs[0][0][0][0]);

    if (tid < 64) {
        int row = b * NTOK + n0 + tid;
        invs[tid] = 1.f / (g_L[row] + g_L[(size_t)BATCH * NTOK + row]);
    }

    float acc[2][2][4];
#pragma unroll
    for (int mb = 0; mb < 2; mb++)
#pragma unroll
        for (int ob = 0; ob < 2; ob++)
#pragma unroll
            for (int i = 0; i < 4; i++) acc[mb][ob][i] = 0.f;

    const float* O0 = g_Osp + (size_t)b * NTOK * DH;
    const float* O1 = g_Osp + ((size_t)BATCH + b) * NTOK * DH;

    auto stage_in = [&](int kt, int s) {
        int o0k = kt * 32;
#pragma unroll
        for (int p = 0; p < 2; p++) {   // As: 64c x 32o = 512 chunks
            int idx = tid + p * 256;
            int cc = idx >> 3, ch = (idx & 7) * 4;
            cp_async16(as_b + (uint32_t)((s * 64 + cc) * 36 + ch) * 4,
                       &Wo[(size_t)(c0 + cc) * DH + o0k + ch]);
        }
#pragma unroll
        for (int p = 0; p < 2; p++) {   // Bs: 2 splits x 512 chunks
            int idx = tid + p * 256;
            int nn = idx >> 3, ch = (idx & 7) * 4;
            size_t go = (size_t)(n0 + nn) * DH + o0k + ch;
            uint32_t so = (uint32_t)(((s * 2 + 0) * 64 + nn) * 36 + ch) * 4;
            cp_async16(bs_b + so, O0 + go);
            cp_async16(bs_b + so + 64 * 36 * 4, O1 + go);
        }
    };

    stage_in(0, 0);
    CP_COMMIT();

    for (int kt = 0; kt < 8; kt++) {
        CP_WAIT0();
        __syncthreads();
        if (kt + 1 < 8) { stage_in(kt + 1, (kt + 1) & 1); CP_COMMIT(); }
        const int s = kt & 1;

#pragma unroll
        for (int k8 = 0; k8 < 4; k8++) {
            const int kb = k8 * 8;
            uint32_t a[2][4];
#pragma unroll
            for (int mb = 0; mb < 2; mb++) {
                int rm = warp_c * 32 + mb * 16 + g;
                a[mb][0] = f2tf32(As[s][rm][kb + lk]);
                a[mb][1] = f2tf32(As[s][rm + 8][kb + lk]);
                a[mb][2] = f2tf32(As[s][rm][kb + 4 + lk]);
                a[mb][3] = f2tf32(As[s][rm + 8][kb + 4 + lk]);
            }
#pragma unroll
            for (int ob = 0; ob < 2; ob++) {
                int nc = warp_nn * 16 + ob * 8 + g;
                float inv = invs[nc];
                uint32_t b0 = f2tf32((Bs[s][0][nc][kb + lk] + Bs[s][1][nc][kb + lk]) * inv);
                uint32_t b1 = f2tf32((Bs[s][0][nc][kb + 4 + lk] + Bs[s][1][nc][kb + 4 + lk]) * inv);
                mma_tf32(acc[0][ob], a[0], b0, b1);
                mma_tf32(acc[1][ob], a[1], b0, b1);
            }
        }
        __syncthreads();
    }

#pragma unroll
    for (int mb = 0; mb < 2; mb++) {
#pragma unroll
        for (int rr = 0; rr < 2; rr++) {
            int c = c0 + warp_c * 32 + mb * 16 + g + rr * 8;
            float bias = bo[c];
#pragma unroll
            for (int ob = 0; ob < 2; ob++) {
                int n = n0 + warp_nn * 16 + ob * 8 + 2 * lk;
                size_t base = ((size_t)b * DH + c) * NTOK + n;
                float2 f = *reinterpret_cast<const float2*>(F + base);
                float2 r;
                r.x = f.x + bias + acc[mb][ob][rr * 2 + 0];
                r.y = f.y + bias + acc[mb][ob][rr * 2 + 1];
                *reinterpret_cast<float2*>(out + base) = r;
            }
        }
    }
}

// ===========================================================================
// Launch
// ===========================================================================
extern "C" void kernel_launch(void* const* d_in, const int* in_sizes, int n_in,
                              void* d_out, int out_size)
{
    const float* F  = (const float*)d_in[0];
    const float* FK = (const float*)d_in[1];
    const float* Wq = (const float*)d_in[2];
    const float* bq = (const float*)d_in[3];
    const float* Wk = (const float*)d_in[4];
    const float* bk = (const float*)d_in[5];
    const float* Wv = (const float*)d_in[6];
    const float* bv = (const float*)d_in[7];
    const float* Wo = (const float*)d_in[8];
    const float* bo = (const float*)d_in[9];
    float* out = (float*)d_out;

    const int attn_smem = (QT + 2 * 2 * KT2) * DP * 2;   // 101,376 bytes
    cudaFuncSetAttribute(attn_kernel, cudaFuncAttributeMaxDynamicSharedMemorySize, attn_smem);

    qproj_kernel<<<dim3(NTOK / 64, DH / 64, BATCH), 256>>>(F, Wq, bq);
    kvproj_kernel<<<dim3(BATCH * NTOK / 64, 2), 256>>>(FK, Wk, bk, Wv, bv);
    attn_kernel<<<dim3(NTOK / QT, BATCH, NSPLIT), 128, attn_smem>>>();
    oproj_kernel<<<dim3(NTOK / 64, DH / 64, BATCH), 256>>>(Wo, bo, F, out);
}

// round 10
// speedup vs baseline: 1.0386x; 1.0263x over previous
#include <cuda_runtime.h>
#include <cuda_bf16.h>
#include <cuda_fp16.h>
#include <cstdint>

// ---------------------------------------------------------------------------
// Problem constants
// ---------------------------------------------------------------------------
#define BATCH   2
#define NTOK    4096
#define DH      256
#define DK      32
#define SCALE   0.125f
#define LOG2E   1.4426950408889634f
#define QSCALE  (SCALE * LOG2E)
#define C2OFF   12.0f

// attention tiling
#define QT      64
#define KT2     32
#define DP      264
#define NSPLIT  2

// ---------------------------------------------------------------------------
// Scratch
// ---------------------------------------------------------------------------
__device__ __nv_bfloat16 g_Q[(size_t)BATCH * NTOK * DH];
__device__ __nv_bfloat16 g_K[(size_t)BATCH * NTOK * DH];
__device__ __half        g_V[(size_t)BATCH * NTOK * DH];
__device__ float         g_Osp[(size_t)NSPLIT * BATCH * NTOK * DH];
__device__ float         g_L[(size_t)NSPLIT * BATCH * NTOK];

// ---------------------------------------------------------------------------
// PTX helpers
// ---------------------------------------------------------------------------
__device__ __forceinline__ void mma16816bf(float* c, const uint32_t* a, uint32_t b0, uint32_t b1) {
    asm volatile(
        "mma.sync.aligned.m16n8k16.row.col.f32.bf16.bf16.f32 "
        "{%0,%1,%2,%3}, {%4,%5,%6,%7}, {%8,%9}, {%0,%1,%2,%3};\n"
        : "+f"(c[0]), "+f"(c[1]), "+f"(c[2]), "+f"(c[3])
        : "r"(a[0]), "r"(a[1]), "r"(a[2]), "r"(a[3]), "r"(b0), "r"(b1));
}

__device__ __forceinline__ void mma16816h(float* c, const uint32_t* a, uint32_t b0, uint32_t b1) {
    asm volatile(
        "mma.sync.aligned.m16n8k16.row.col.f32.f16.f16.f32 "
        "{%0,%1,%2,%3}, {%4,%5,%6,%7}, {%8,%9}, {%0,%1,%2,%3};\n"
        : "+f"(c[0]), "+f"(c[1]), "+f"(c[2]), "+f"(c[3])
        : "r"(a[0]), "r"(a[1]), "r"(a[2]), "r"(a[3]), "r"(b0), "r"(b1));
}

__device__ __forceinline__ void mma_tf32(float* c, const uint32_t* a, uint32_t b0, uint32_t b1) {
    asm volatile(
        "mma.sync.aligned.m16n8k8.row.col.f32.tf32.tf32.f32 "
        "{%0,%1,%2,%3}, {%4,%5,%6,%7}, {%8,%9}, {%0,%1,%2,%3};\n"
        : "+f"(c[0]), "+f"(c[1]), "+f"(c[2]), "+f"(c[3])
        : "r"(a[0]), "r"(a[1]), "r"(a[2]), "r"(a[3]), "r"(b0), "r"(b1));
}

__device__ __forceinline__ uint32_t f2tf32(float f) {
    uint32_t u;
    asm("cvt.rna.tf32.f32 %0, %1;" : "=r"(u) : "f"(f));
    return u;
}

__device__ __forceinline__ void ldsm_x4(uint32_t* r, uint32_t addr) {
    asm volatile("ldmatrix.sync.aligned.m8n8.x4.shared.b16 {%0,%1,%2,%3}, [%4];"
                 : "=r"(r[0]), "=r"(r[1]), "=r"(r[2]), "=r"(r[3]) : "r"(addr));
}

__device__ __forceinline__ void ldsm_x4_t(uint32_t* r, uint32_t addr) {
    asm volatile("ldmatrix.sync.aligned.m8n8.x4.trans.shared.b16 {%0,%1,%2,%3}, [%4];"
                 : "=r"(r[0]), "=r"(r[1]), "=r"(r[2]), "=r"(r[3]) : "r"(addr));
}

__device__ __forceinline__ uint32_t pack_f16(float hi, float lo) {
    uint32_t d;
    asm("cvt.rn.f16x2.f32 %0, %1, %2;" : "=r"(d) : "f"(hi), "f"(lo));
    return d;
}
__device__ __forceinline__ uint32_t ex2_f16x2(uint32_t s) {
    uint32_t d;
    asm("ex2.approx.f16x2 %0, %1;" : "=r"(d) : "r"(s));
    return d;
}

__device__ __forceinline__ void cp_async16(uint32_t smem, const void* gptr) {
    asm volatile("cp.async.cg.shared.global [%0], [%1], 16;" :: "r"(smem), "l"(gptr));
}
#define CP_COMMIT() asm volatile("cp.async.commit_group;")
#define CP_WAIT0()  asm volatile("cp.async.wait_group 0;")

// ===========================================================================
// Kernel 1: fused Q/K/V projections (one launch, branch on blockIdx.x).
//   blocks [0, 512): Q projection, tf32 MMA, 64n x 64o tiles, 64-wide k stages
//   blocks [512, 768): K (bf16) / V (f16) projection, weights in registers
//   dynamic smem 71,680 B.
// ===========================================================================
__global__ void __launch_bounds__(256) qkvproj_kernel(
    const float* __restrict__ F,  const float* __restrict__ FK,
    const float* __restrict__ Wq, const float* __restrict__ bq,
    const float* __restrict__ Wk, const float* __restrict__ bk,
    const float* __restrict__ Wv, const float* __restrict__ bv)
{
    extern __shared__ __align__(16) float dyn[];
    const int bid = blockIdx.x;
    const int tid = threadIdx.x;

    if (bid < 512) {
        // ----- Q projection -----
        const int n0 = (bid & 63) * 64;
        const int o0 = ((bid >> 6) & 3) * 64;
        const int b  = bid >> 8;
        const int warp = tid >> 5, lane = tid & 31;
        const int warp_n = warp & 1, warp_o = warp >> 1;
        const int g = lane >> 2, lk = lane & 3;

        float* Asp = dyn;                 // [2][64][72]
        float* Wsp = dyn + 2 * 64 * 72;   // [2][64][68]
        const uint32_t as_b = (uint32_t)__cvta_generic_to_shared(Asp);
        const uint32_t ws_b = (uint32_t)__cvta_generic_to_shared(Wsp);

        float acc[2][2][4];
#pragma unroll
        for (int mb = 0; mb < 2; mb++)
#pragma unroll
            for (int ob = 0; ob < 2; ob++)
#pragma unroll
                for (int i = 0; i < 4; i++) acc[mb][ob][i] = 0.f;

        const float* Fb = F + (size_t)b * DH * NTOK;

        auto stage_in = [&](int kt, int s) {
            int c0 = kt * 64;
#pragma unroll
            for (int p = 0; p < 4; p++) {
                int idx = tid + p * 256;
                int cc = idx >> 4, ch = (idx & 15) * 4;
                cp_async16(as_b + (uint32_t)((s * 64 + cc) * 72 + ch) * 4,
                           &Fb[(size_t)(c0 + cc) * NTOK + n0 + ch]);
            }
#pragma unroll
            for (int p = 0; p < 4; p++) {
                int idx = tid + p * 256;
                int oo = idx >> 4, ch = (idx & 15) * 4;
                cp_async16(ws_b + (uint32_t)((s * 64 + oo) * 68 + ch) * 4,
                           &Wq[(size_t)(o0 + oo) * DH + c0 + ch]);
            }
        };

        stage_in(0, 0);
        CP_COMMIT();

        for (int kt = 0; kt < 4; kt++) {
            CP_WAIT0();
            __syncthreads();
            if (kt + 1 < 4) { stage_in(kt + 1, (kt + 1) & 1); CP_COMMIT(); }
            const int s = kt & 1;

#pragma unroll
            for (int k8 = 0; k8 < 8; k8++) {
                const int kb = k8 * 8;
                uint32_t a[2][4];
#pragma unroll
                for (int mb = 0; mb < 2; mb++) {
                    int rm = warp_n * 32 + mb * 16 + g;
                    a[mb][0] = f2tf32(Asp[(s * 64 + kb + lk) * 72 + rm]);
                    a[mb][1] = f2tf32(Asp[(s * 64 + kb + lk) * 72 + rm + 8]);
                    a[mb][2] = f2tf32(Asp[(s * 64 + kb + 4 + lk) * 72 + rm]);
                    a[mb][3] = f2tf32(Asp[(s * 64 + kb + 4 + lk) * 72 + rm + 8]);
                }
#pragma unroll
                for (int ob = 0; ob < 2; ob++) {
                    int oc = warp_o * 16 + ob * 8 + g;
                    uint32_t b0 = f2tf32(Wsp[(s * 64 + oc) * 68 + kb + lk]);
                    uint32_t b1 = f2tf32(Wsp[(s * 64 + oc) * 68 + kb + 4 + lk]);
                    mma_tf32(acc[0][ob], a[0], b0, b1);
                    mma_tf32(acc[1][ob], a[1], b0, b1);
                }
            }
            __syncthreads();
        }

#pragma unroll
        for (int ob = 0; ob < 2; ob++) {
            int o = o0 + warp_o * 16 + ob * 8 + 2 * lk;
            float bv0 = bq[o], bv1 = bq[o + 1];
#pragma unroll
            for (int mb = 0; mb < 2; mb++) {
                int r = n0 + warp_n * 32 + mb * 16 + g;
                __nv_bfloat162 lo = __floats2bfloat162_rn(
                    (acc[mb][ob][0] + bv0) * QSCALE, (acc[mb][ob][1] + bv1) * QSCALE);
                __nv_bfloat162 hi = __floats2bfloat162_rn(
                    (acc[mb][ob][2] + bv0) * QSCALE, (acc[mb][ob][3] + bv1) * QSCALE);
                *reinterpret_cast<uint32_t*>(&g_Q[((size_t)b * NTOK + r) * DH + o]) =
                    *reinterpret_cast<uint32_t*>(&lo);
                *reinterpret_cast<uint32_t*>(&g_Q[((size_t)b * NTOK + r + 8) * DH + o]) =
                    *reinterpret_cast<uint32_t*>(&hi);
            }
        }
    } else {
        // ----- K / V projection -----
        const int bid2 = bid - 512;
        const bool isK = (bid2 < 128);
        const float* W    = isK ? Wk : Wv;
        const float* bias = isK ? bk : bv;

        const int t0 = (bid2 & 127) * 64;
        const int b  = t0 >> 12;
        const int n0 = t0 & (NTOK - 1);
        const int o  = tid;

        float* xs = dyn;   // [64][36]

        float w[32];
#pragma unroll
        for (int i = 0; i < 8; i++) {
            float4 v = *reinterpret_cast<const float4*>(&W[(size_t)o * DK + i * 4]);
            w[i * 4 + 0] = v.x; w[i * 4 + 1] = v.y; w[i * 4 + 2] = v.z; w[i * 4 + 3] = v.w;
        }
        const float bb = bias[o];

        const float* FKb = FK + (size_t)b * DK * NTOK;
#pragma unroll
        for (int p = 0; p < 2; p++) {
            int idx = tid + p * 256;
            int c = idx >> 4, t4 = (idx & 15) * 4;
            float4 v = *reinterpret_cast<const float4*>(&FKb[(size_t)c * NTOK + n0 + t4]);
            xs[(t4 + 0) * 36 + c] = v.x; xs[(t4 + 1) * 36 + c] = v.y;
            xs[(t4 + 2) * 36 + c] = v.z; xs[(t4 + 3) * 36 + c] = v.w;
        }
        __syncthreads();

        for (int tok = 0; tok < 64; tok++) {
            float acc = bb;
#pragma unroll
            for (int i = 0; i < 8; i++) {
                float4 x = *reinterpret_cast<float4*>(&xs[tok * 36 + i * 4]);
                acc += x.x * w[i * 4 + 0] + x.y * w[i * 4 + 1]
                     + x.z * w[i * 4 + 2] + x.w * w[i * 4 + 3];
            }
            size_t di = ((size_t)b * NTOK + n0 + tok) * DH + o;
            if (isK) g_K[di] = __float2bfloat16(acc);
            else     g_V[di] = __float2half(acc);
        }
    }
}

// ===========================================================================
// Kernel 3: flash attention, split-KV, Q fragments register-resident.
//   (frozen)
// ===========================================================================
__global__ void __launch_bounds__(128) attn_kernel()
{
    extern __shared__ __align__(16) __nv_bfloat16 sm[];
    __nv_bfloat16* Qs = sm;

    const int b     = blockIdx.y;
    const int split = blockIdx.z;
    const int q0    = blockIdx.x * QT;
    const int tid = threadIdx.x, warp = tid >> 5, lane = tid & 31;

    const int kglob0 = split * (NTOK / NSPLIT);

    const __nv_bfloat16* Qg = g_Q + ((size_t)b * NTOK + q0) * DH;
    const __nv_bfloat16* Kg = g_K + (size_t)b * NTOK * DH;
    const __half*        Vg = g_V + (size_t)b * NTOK * DH;

    const uint32_t smb = (uint32_t)__cvta_generic_to_shared(sm);

    const int qrow = warp * 16 + (lane & 15);
    const int qcol = (lane >> 4) * 8;
    const uint32_t qaddr = smb + (uint32_t)(qrow * DP + qcol) * 2;
    const int krow = (lane & 7) + ((lane >> 4) << 3);
    const int kcol = ((lane >> 3) & 1) * 8;
    const int vrow = lane & 15;
    const int vcol = (lane >> 4) * 8;

    auto kbase = [&](int s) -> uint32_t { return smb + (uint32_t)(QT + s * 2 * KT2) * DP * 2; };

    auto prefetch = [&](int k0, int s) {
        uint32_t kb = kbase(s);
        uint32_t vb = kb + KT2 * DP * 2;
#pragma unroll
        for (int i = 0; i < 8; i++) {
            int idx = tid + i * 128;
            int r = idx >> 5, c = (idx & 31) * 8;
            uint32_t so = (uint32_t)(r * DP + c) * 2;
            cp_async16(kb + so, Kg + (size_t)(k0 + r) * DH + c);
            cp_async16(vb + so, Vg + (size_t)(k0 + r) * DH + c);
        }
    };

    prefetch(kglob0, 0);
    CP_COMMIT();

    for (int idx = tid; idx < QT * 32; idx += 128) {
        int r = idx >> 5, c = (idx & 31) * 8;
        *reinterpret_cast<uint4*>(Qs + r * DP + c) =
            *reinterpret_cast<const uint4*>(Qg + (size_t)r * DH + c);
    }
    __syncthreads();

    uint32_t qf[16][4];
#pragma unroll
    for (int d0 = 0; d0 < 16; d0++)
        ldsm_x4(qf[d0], qaddr + (uint32_t)(d0 * 16) * 2);

    float acc[32][4];
#pragma unroll
    for (int i = 0; i < 32; i++)
#pragma unroll
        for (int j = 0; j < 4; j++) acc[i][j] = 0.f;
    float lsum[4] = {0.f, 0.f, 0.f, 0.f};
    const uint32_t ONES = 0x3C003C00u;

    const int NT = (NTOK / NSPLIT) / KT2;   // 64
    for (int t = 0; t < NT; t++) {
        CP_WAIT0();
        __syncthreads();
        if (t + 1 < NT) { prefetch(kglob0 + (t + 1) * KT2, (t + 1) & 1); CP_COMMIT(); }

        const uint32_t ksa = kbase(t & 1);
        const uint32_t vsa = ksa + KT2 * DP * 2;

        float S[4][4];
#pragma unroll
        for (int j = 0; j < 4; j++)
#pragma unroll
            for (int i = 0; i < 4; i++) S[j][i] = -C2OFF;

#pragma unroll
        for (int d0 = 0; d0 < 16; d0++) {
#pragma unroll
            for (int j = 0; j < 4; j += 2) {
                uint32_t bk4[4];
                ldsm_x4(bk4, ksa + (uint32_t)((j * 8 + krow) * DP + d0 * 16 + kcol) * 2);
                mma16816bf(S[j],     qf[d0], bk4[0], bk4[1]);
                mma16816bf(S[j + 1], qf[d0], bk4[2], bk4[3]);
            }
        }

        uint32_t Pa[2][4];
#pragma unroll
        for (int j = 0; j < 4; j++) {
            uint32_t p01 = ex2_f16x2(pack_f16(S[j][1], S[j][0]));
            uint32_t p23 = ex2_f16x2(pack_f16(S[j][3], S[j][2]));
            int kk = j >> 1;
            if ((j & 1) == 0) { Pa[kk][0] = p01; Pa[kk][1] = p23; }
            else              { Pa[kk][2] = p01; Pa[kk][3] = p23; }
        }

#pragma unroll
        for (int kk = 0; kk < 2; kk++) mma16816h(lsum, Pa[kk], ONES, ONES);

#pragma unroll
        for (int dt = 0; dt < 32; dt += 2) {
#pragma unroll
            for (int kk = 0; kk < 2; kk++) {
                uint32_t bv4[4];
                ldsm_x4_t(bv4, vsa + (uint32_t)((kk * 16 + vrow) * DP + dt * 8 + vcol) * 2);
                mma16816h(acc[dt],     Pa[kk], bv4[0], bv4[1]);
                mma16816h(acc[dt + 1], Pa[kk], bv4[2], bv4[3]);
            }
        }
    }

    float* Ob = g_Osp + ((size_t)split * BATCH + b) * NTOK * DH;
    const int r0 = q0 + warp * 16 + (lane >> 2);
    const int r1 = r0 + 8;
    const int dcol = (lane & 3) * 2;
#pragma unroll
    for (int dt = 0; dt < 32; dt++) {
        int d = dt * 8 + dcol;
        *reinterpret_cast<float2*>(Ob + (size_t)r0 * DH + d) =
            make_float2(acc[dt][0], acc[dt][1]);
        *reinterpret_cast<float2*>(Ob + (size_t)r1 * DH + d) =
            make_float2(acc[dt][2], acc[dt][3]);
    }
    if ((lane & 3) == 0) {
        g_L[((size_t)split * BATCH + b) * NTOK + r0] = lsum[0];
        g_L[((size_t)split * BATCH + b) * NTOK + r1] = lsum[2];
    }
}

// ===========================================================================
// Kernel 4: output projection + residual, merge fused.
//   CTA 128c x 64n, grid 256 (O re-read 2x not 4x), 8 warps (4c x 2n),
//   warp tile 32c x 32n. Dynamic smem 73,728 B.
// ===========================================================================
__global__ void __launch_bounds__(256) oproj_kernel(
    const float* __restrict__ Wo, const float* __restrict__ bo,
    const float* __restrict__ F, float* __restrict__ out)
{
    extern __shared__ __align__(16) float dyn[];
    __shared__ float invs[64];

    const int b  = blockIdx.z;
    const int n0 = blockIdx.x * 64;
    const int c0 = blockIdx.y * 128;
    const int tid = threadIdx.x, warp = tid >> 5, lane = tid & 31;
    const int warp_c = warp & 3, warp_n = warp >> 2;
    const int g = lane >> 2, lk = lane & 3;

    float* Asp = dyn;                  // [2][128][36]
    float* Bsp = dyn + 2 * 128 * 36;   // [2][2][64][36]
    const uint32_t as_b = (uint32_t)__cvta_generic_to_shared(Asp);
    const uint32_t bs_b = (uint32_t)__cvta_generic_to_shared(Bsp);

    if (tid < 64) {
        int row = b * NTOK + n0 + tid;
        invs[tid] = 1.f / (g_L[row] + g_L[(size_t)BATCH * NTOK + row]);
    }

    float acc[2][4][4];
#pragma unroll
    for (int mb = 0; mb < 2; mb++)
#pragma unroll
        for (int ob = 0; ob < 4; ob++)
#pragma unroll
            for (int i = 0; i < 4; i++) acc[mb][ob][i] = 0.f;

    const float* O0 = g_Osp + (size_t)b * NTOK * DH;
    const float* O1 = g_Osp + ((size_t)BATCH + b) * NTOK * DH;

    auto stage_in = [&](int kt, int s) {
        int o0k = kt * 32;
#pragma unroll
        for (int p = 0; p < 4; p++) {   // As: 128c x 32o = 1024 chunks
            int idx = tid + p * 256;
            int cc = idx >> 3, ch = (idx & 7) * 4;
            cp_async16(as_b + (uint32_t)((s * 128 + cc) * 36 + ch) * 4,
                       &Wo[(size_t)(c0 + cc) * DH + o0k + ch]);
        }
#pragma unroll
        for (int p = 0; p < 2; p++) {   // Bs: 2 splits x 64n x 32o = 1024 chunks
            int idx = tid + p * 256;
            int nn = idx >> 3, ch = (idx & 7) * 4;
            size_t go = (size_t)(n0 + nn) * DH + o0k + ch;
            uint32_t so = (uint32_t)(((s * 2 + 0) * 64 + nn) * 36 + ch) * 4;
            cp_async16(bs_b + so, O0 + go);
            cp_async16(bs_b + so + 64 * 36 * 4, O1 + go);
        }
    };

    stage_in(0, 0);
    CP_COMMIT();

    for (int kt = 0; kt < 8; kt++) {
        CP_WAIT0();
        __syncthreads();
        if (kt + 1 < 8) { stage_in(kt + 1, (kt + 1) & 1); CP_COMMIT(); }
        const int s = kt & 1;

#pragma unroll
        for (int k8 = 0; k8 < 4; k8++) {
            const int kb = k8 * 8;
            uint32_t a[2][4];
#pragma unroll
            for (int mb = 0; mb < 2; mb++) {
                int rm = warp_c * 32 + mb * 16 + g;
                a[mb][0] = f2tf32(Asp[(s * 128 + rm) * 36 + kb + lk]);
                a[mb][1] = f2tf32(Asp[(s * 128 + rm + 8) * 36 + kb + lk]);
                a[mb][2] = f2tf32(Asp[(s * 128 + rm) * 36 + kb + 4 + lk]);
                a[mb][3] = f2tf32(Asp[(s * 128 + rm + 8) * 36 + kb + 4 + lk]);
            }
#pragma unroll
            for (int ob = 0; ob < 4; ob++) {
                int nc = warp_n * 32 + ob * 8 + g;
                float inv = invs[nc];
                float s0 = Bsp[((s * 2 + 0) * 64 + nc) * 36 + kb + lk]
                         + Bsp[((s * 2 + 1) * 64 + nc) * 36 + kb + lk];
                float s1 = Bsp[((s * 2 + 0) * 64 + nc) * 36 + kb + 4 + lk]
                         + Bsp[((s * 2 + 1) * 64 + nc) * 36 + kb + 4 + lk];
                uint32_t b0 = f2tf32(s0 * inv);
                uint32_t b1 = f2tf32(s1 * inv);
                mma_tf32(acc[0][ob], a[0], b0, b1);
                mma_tf32(acc[1][ob], a[1], b0, b1);
            }
        }
        __syncthreads();
    }

#pragma unroll
    for (int mb = 0; mb < 2; mb++) {
#pragma unroll
        for (int rr = 0; rr < 2; rr++) {
            int c = c0 + warp_c * 32 + mb * 16 + g + rr * 8;
            float bias = bo[c];
#pragma unroll
            for (int ob = 0; ob < 4; ob++) {
                int n = n0 + warp_n * 32 + ob * 8 + 2 * lk;
                size_t base = ((size_t)b * DH + c) * NTOK + n;
                float2 f = *reinterpret_cast<const float2*>(F + base);
                float2 r;
                r.x = f.x + bias + acc[mb][ob][rr * 2 + 0];
                r.y = f.y + bias + acc[mb][ob][rr * 2 + 1];
                *reinterpret_cast<float2*>(out + base) = r;
            }
        }
    }
}

// ===========================================================================
// Launch
// ===========================================================================
extern "C" void kernel_launch(void* const* d_in, const int* in_sizes, int n_in,
                              void* d_out, int out_size)
{
    const float* F  = (const float*)d_in[0];
    const float* FK = (const float*)d_in[1];
    const float* Wq = (const float*)d_in[2];
    const float* bq = (const float*)d_in[3];
    const float* Wk = (const float*)d_in[4];
    const float* bk = (const float*)d_in[5];
    const float* Wv = (const float*)d_in[6];
    const float* bv = (const float*)d_in[7];
    const float* Wo = (const float*)d_in[8];
    const float* bo = (const float*)d_in[9];
    float* out = (float*)d_out;

    const int qkv_smem   = (2 * 64 * 72 + 2 * 64 * 68) * 4;          // 71,680
    const int attn_smem  = (QT + 2 * 2 * KT2) * DP * 2;              // 101,376
    const int oproj_smem = (2 * 128 * 36 + 2 * 2 * 64 * 36) * 4;     // 73,728

    cudaFuncSetAttribute(qkvproj_kernel, cudaFuncAttributeMaxDynamicSharedMemorySize, qkv_smem);
    cudaFuncSetAttribute(attn_kernel,    cudaFuncAttributeMaxDynamicSharedMemorySize, attn_smem);
    cudaFuncSetAttribute(oproj_kernel,   cudaFuncAttributeMaxDynamicSharedMemorySize, oproj_smem);

    qkvproj_kernel<<<768, 256, qkv_smem>>>(F, FK, Wq, bq, Wk, bk, Wv, bv);
    attn_kernel<<<dim3(NTOK / QT, BATCH, NSPLIT), 128, attn_smem>>>();
    oproj_kernel<<<dim3(NTOK / 64, DH / 128, BATCH), 256, oproj_smem>>>(Wo, bo, F, out);
}

// round 11
// speedup vs baseline: 1.0526x; 1.0135x over previous
#include <cuda_runtime.h>
#include <cuda_bf16.h>
#include <cuda_fp16.h>
#include <cstdint>

// ---------------------------------------------------------------------------
// Problem constants
// ---------------------------------------------------------------------------
#define BATCH   2
#define NTOK    4096
#define DH      256
#define DK      32
#define SCALE   0.125f
#define LOG2E   1.4426950408889634f
#define QSCALE  (SCALE * LOG2E)
#define C2OFF   12.0f

// attention tiling
#define QT      64
#define KT2     32
#define DP      264
#define NSPLIT  2

// ---------------------------------------------------------------------------
// Scratch
// ---------------------------------------------------------------------------
__device__ __nv_bfloat16 g_Q[(size_t)BATCH * NTOK * DH];
__device__ __nv_bfloat16 g_K[(size_t)BATCH * NTOK * DH];
__device__ __half        g_V[(size_t)BATCH * NTOK * DH];
__device__ float         g_Osp[(size_t)NSPLIT * BATCH * NTOK * DH];
__device__ float         g_L[(size_t)NSPLIT * BATCH * NTOK];

// ---------------------------------------------------------------------------
// PTX helpers
// ---------------------------------------------------------------------------
__device__ __forceinline__ void mma16816bf(float* c, const uint32_t* a, uint32_t b0, uint32_t b1) {
    asm volatile(
        "mma.sync.aligned.m16n8k16.row.col.f32.bf16.bf16.f32 "
        "{%0,%1,%2,%3}, {%4,%5,%6,%7}, {%8,%9}, {%0,%1,%2,%3};\n"
        : "+f"(c[0]), "+f"(c[1]), "+f"(c[2]), "+f"(c[3])
        : "r"(a[0]), "r"(a[1]), "r"(a[2]), "r"(a[3]), "r"(b0), "r"(b1));
}

__device__ __forceinline__ void mma16816h(float* c, const uint32_t* a, uint32_t b0, uint32_t b1) {
    asm volatile(
        "mma.sync.aligned.m16n8k16.row.col.f32.f16.f16.f32 "
        "{%0,%1,%2,%3}, {%4,%5,%6,%7}, {%8,%9}, {%0,%1,%2,%3};\n"
        : "+f"(c[0]), "+f"(c[1]), "+f"(c[2]), "+f"(c[3])
        : "r"(a[0]), "r"(a[1]), "r"(a[2]), "r"(a[3]), "r"(b0), "r"(b1));
}

__device__ __forceinline__ void mma_tf32(float* c, const uint32_t* a, uint32_t b0, uint32_t b1) {
    asm volatile(
        "mma.sync.aligned.m16n8k8.row.col.f32.tf32.tf32.f32 "
        "{%0,%1,%2,%3}, {%4,%5,%6,%7}, {%8,%9}, {%0,%1,%2,%3};\n"
        : "+f"(c[0]), "+f"(c[1]), "+f"(c[2]), "+f"(c[3])
        : "r"(a[0]), "r"(a[1]), "r"(a[2]), "r"(a[3]), "r"(b0), "r"(b1));
}

__device__ __forceinline__ uint32_t f2tf32(float f) {
    uint32_t u;
    asm("cvt.rna.tf32.f32 %0, %1;" : "=r"(u) : "f"(f));
    return u;
}

__device__ __forceinline__ void ldsm_x4(uint32_t* r, uint32_t addr) {
    asm volatile("ldmatrix.sync.aligned.m8n8.x4.shared.b16 {%0,%1,%2,%3}, [%4];"
                 : "=r"(r[0]), "=r"(r[1]), "=r"(r[2]), "=r"(r[3]) : "r"(addr));
}

__device__ __forceinline__ void ldsm_x4_t(uint32_t* r, uint32_t addr) {
    asm volatile("ldmatrix.sync.aligned.m8n8.x4.trans.shared.b16 {%0,%1,%2,%3}, [%4];"
                 : "=r"(r[0]), "=r"(r[1]), "=r"(r[2]), "=r"(r[3]) : "r"(addr));
}

__device__ __forceinline__ uint32_t pack_f16(float hi, float lo) {
    uint32_t d;
    asm("cvt.rn.f16x2.f32 %0, %1, %2;" : "=r"(d) : "f"(hi), "f"(lo));
    return d;
}
__device__ __forceinline__ uint32_t ex2_f16x2(uint32_t s) {
    uint32_t d;
    asm("ex2.approx.f16x2 %0, %1;" : "=r"(d) : "r"(s));
    return d;
}

__device__ __forceinline__ void cp_async16(uint32_t smem, const void* gptr) {
    asm volatile("cp.async.cg.shared.global [%0], [%1], 16;" :: "r"(smem), "l"(gptr));
}
#define CP_COMMIT() asm volatile("cp.async.commit_group;")
#define CP_WAIT0()  asm volatile("cp.async.wait_group 0;")

// ===========================================================================
// Kernel 1: fused Q/K/V projections.
//   blocks [0, 256): Q projection, CTA 64n x 128o, warp tile 32x32,
//                    32-wide k stages (8 iterations). smem 55,296 B.
//   blocks [256, 512): K (bf16) / V (f16) projection, weights in registers.
// ===========================================================================
__global__ void __launch_bounds__(256) qkvproj_kernel(
    const float* __restrict__ F,  const float* __restrict__ FK,
    const float* __restrict__ Wq, const float* __restrict__ bq,
    const float* __restrict__ Wk, const float* __restrict__ bk,
    const float* __restrict__ Wv, const float* __restrict__ bv)
{
    extern __shared__ __align__(16) float dyn[];
    const int bid = blockIdx.x;
    const int tid = threadIdx.x;

    if (bid < 256) {
        // ----- Q projection -----
        const int n0 = (bid & 63) * 64;
        const int o0 = ((bid >> 6) & 1) * 128;
        const int b  = bid >> 7;
        const int warp = tid >> 5, lane = tid & 31;
        const int warp_n = warp & 1, warp_o = warp >> 1;   // 2n x 4o
        const int g = lane >> 2, lk = lane & 3;

        float* Asp = dyn;                 // [2][32][72]  (c-major, n fast)
        float* Wsp = dyn + 2 * 32 * 72;   // [2][128][36] (o-major, c fast)
        const uint32_t as_b = (uint32_t)__cvta_generic_to_shared(Asp);
        const uint32_t ws_b = (uint32_t)__cvta_generic_to_shared(Wsp);

        float acc[2][4][4];
#pragma unroll
        for (int mb = 0; mb < 2; mb++)
#pragma unroll
            for (int ob = 0; ob < 4; ob++)
#pragma unroll
                for (int i = 0; i < 4; i++) acc[mb][ob][i] = 0.f;

        const float* Fb = F + (size_t)b * DH * NTOK;

        auto stage_in = [&](int kt, int s) {
            int c0 = kt * 32;
#pragma unroll
            for (int p = 0; p < 2; p++) {   // As: 32c x 64n = 512 chunks
                int idx = tid + p * 256;
                int cc = idx >> 4, ch = (idx & 15) * 4;
                cp_async16(as_b + (uint32_t)((s * 32 + cc) * 72 + ch) * 4,
                           &Fb[(size_t)(c0 + cc) * NTOK + n0 + ch]);
            }
#pragma unroll
            for (int p = 0; p < 4; p++) {   // Ws: 128o x 32c = 1024 chunks
                int idx = tid + p * 256;
                int oo = idx >> 3, ch = (idx & 7) * 4;
                cp_async16(ws_b + (uint32_t)((s * 128 + oo) * 36 + ch) * 4,
                           &Wq[(size_t)(o0 + oo) * DH + c0 + ch]);
            }
        };

        stage_in(0, 0);
        CP_COMMIT();

        for (int kt = 0; kt < 8; kt++) {
            CP_WAIT0();
            __syncthreads();
            if (kt + 1 < 8) { stage_in(kt + 1, (kt + 1) & 1); CP_COMMIT(); }
            const int s = kt & 1;

#pragma unroll
            for (int k8 = 0; k8 < 4; k8++) {
                const int kb = k8 * 8;
                uint32_t a[2][4];
#pragma unroll
                for (int mb = 0; mb < 2; mb++) {
                    int rm = warp_n * 32 + mb * 16 + g;
                    a[mb][0] = f2tf32(Asp[(s * 32 + kb + lk) * 72 + rm]);
                    a[mb][1] = f2tf32(Asp[(s * 32 + kb + lk) * 72 + rm + 8]);
                    a[mb][2] = f2tf32(Asp[(s * 32 + kb + 4 + lk) * 72 + rm]);
                    a[mb][3] = f2tf32(Asp[(s * 32 + kb + 4 + lk) * 72 + rm + 8]);
                }
#pragma unroll
                for (int ob = 0; ob < 4; ob++) {
                    int oc = warp_o * 32 + ob * 8 + g;
                    uint32_t b0 = f2tf32(Wsp[(s * 128 + oc) * 36 + kb + lk]);
                    uint32_t b1 = f2tf32(Wsp[(s * 128 + oc) * 36 + kb + 4 + lk]);
                    mma_tf32(acc[0][ob], a[0], b0, b1);
                    mma_tf32(acc[1][ob], a[1], b0, b1);
                }
            }
            __syncthreads();
        }

#pragma unroll
        for (int ob = 0; ob < 4; ob++) {
            int o = o0 + warp_o * 32 + ob * 8 + 2 * lk;
            float bv0 = bq[o], bv1 = bq[o + 1];
#pragma unroll
            for (int mb = 0; mb < 2; mb++) {
                int r = n0 + warp_n * 32 + mb * 16 + g;
                __nv_bfloat162 lo = __floats2bfloat162_rn(
                    (acc[mb][ob][0] + bv0) * QSCALE, (acc[mb][ob][1] + bv1) * QSCALE);
                __nv_bfloat162 hi = __floats2bfloat162_rn(
                    (acc[mb][ob][2] + bv0) * QSCALE, (acc[mb][ob][3] + bv1) * QSCALE);
                *reinterpret_cast<uint32_t*>(&g_Q[((size_t)b * NTOK + r) * DH + o]) =
                    *reinterpret_cast<uint32_t*>(&lo);
                *reinterpret_cast<uint32_t*>(&g_Q[((size_t)b * NTOK + r + 8) * DH + o]) =
                    *reinterpret_cast<uint32_t*>(&hi);
            }
        }
    } else {
        // ----- K / V projection -----
        const int bid2 = bid - 256;
        const bool isK = (bid2 < 128);
        const float* W    = isK ? Wk : Wv;
        const float* bias = isK ? bk : bv;

        const int t0 = (bid2 & 127) * 64;
        const int b  = t0 >> 12;
        const int n0 = t0 & (NTOK - 1);
        const int o  = tid;

        float* xs = dyn;   // [64][36]

        float w[32];
#pragma unroll
        for (int i = 0; i < 8; i++) {
            float4 v = *reinterpret_cast<const float4*>(&W[(size_t)o * DK + i * 4]);
            w[i * 4 + 0] = v.x; w[i * 4 + 1] = v.y; w[i * 4 + 2] = v.z; w[i * 4 + 3] = v.w;
        }
        const float bb = bias[o];

        const float* FKb = FK + (size_t)b * DK * NTOK;
#pragma unroll
        for (int p = 0; p < 2; p++) {
            int idx = tid + p * 256;
            int c = idx >> 4, t4 = (idx & 15) * 4;
            float4 v = *reinterpret_cast<const float4*>(&FKb[(size_t)c * NTOK + n0 + t4]);
            xs[(t4 + 0) * 36 + c] = v.x; xs[(t4 + 1) * 36 + c] = v.y;
            xs[(t4 + 2) * 36 + c] = v.z; xs[(t4 + 3) * 36 + c] = v.w;
        }
        __syncthreads();

        for (int tok = 0; tok < 64; tok++) {
            float acc = bb;
#pragma unroll
            for (int i = 0; i < 8; i++) {
                float4 x = *reinterpret_cast<float4*>(&xs[tok * 36 + i * 4]);
                acc += x.x * w[i * 4 + 0] + x.y * w[i * 4 + 1]
                     + x.z * w[i * 4 + 2] + x.w * w[i * 4 + 3];
            }
            size_t di = ((size_t)b * NTOK + n0 + tok) * DH + o;
            if (isK) g_K[di] = __float2bfloat16(acc);
            else     g_V[di] = __float2half(acc);
        }
    }
}

// ===========================================================================
// Kernel 3: flash attention, split-KV, Q fragments register-resident.
//   Row sums via HADD2 on the FMA pipe (tensor pipe is the binder).
// ===========================================================================
__global__ void __launch_bounds__(128) attn_kernel()
{
    extern __shared__ __align__(16) __nv_bfloat16 sm[];
    __nv_bfloat16* Qs = sm;

    const int b     = blockIdx.y;
    const int split = blockIdx.z;
    const int q0    = blockIdx.x * QT;
    const int tid = threadIdx.x, warp = tid >> 5, lane = tid & 31;

    const int kglob0 = split * (NTOK / NSPLIT);

    const __nv_bfloat16* Qg = g_Q + ((size_t)b * NTOK + q0) * DH;
    const __nv_bfloat16* Kg = g_K + (size_t)b * NTOK * DH;
    const __half*        Vg = g_V + (size_t)b * NTOK * DH;

    const uint32_t smb = (uint32_t)__cvta_generic_to_shared(sm);

    const int qrow = warp * 16 + (lane & 15);
    const int qcol = (lane >> 4) * 8;
    const uint32_t qaddr = smb + (uint32_t)(qrow * DP + qcol) * 2;
    const int krow = (lane & 7) + ((lane >> 4) << 3);
    const int kcol = ((lane >> 3) & 1) * 8;
    const int vrow = lane & 15;
    const int vcol = (lane >> 4) * 8;

    auto kbase = [&](int s) -> uint32_t { return smb + (uint32_t)(QT + s * 2 * KT2) * DP * 2; };

    auto prefetch = [&](int k0, int s) {
        uint32_t kb = kbase(s);
        uint32_t vb = kb + KT2 * DP * 2;
#pragma unroll
        for (int i = 0; i < 8; i++) {
            int idx = tid + i * 128;
            int r = idx >> 5, c = (idx & 31) * 8;
            uint32_t so = (uint32_t)(r * DP + c) * 2;
            cp_async16(kb + so, Kg + (size_t)(k0 + r) * DH + c);
            cp_async16(vb + so, Vg + (size_t)(k0 + r) * DH + c);
        }
    };

    prefetch(kglob0, 0);
    CP_COMMIT();

    for (int idx = tid; idx < QT * 32; idx += 128) {
        int r = idx >> 5, c = (idx & 31) * 8;
        *reinterpret_cast<uint4*>(Qs + r * DP + c) =
            *reinterpret_cast<const uint4*>(Qg + (size_t)r * DH + c);
    }
    __syncthreads();

    uint32_t qf[16][4];
#pragma unroll
    for (int d0 = 0; d0 < 16; d0++)
        ldsm_x4(qf[d0], qaddr + (uint32_t)(d0 * 16) * 2);

    float acc[32][4];
#pragma unroll
    for (int i = 0; i < 32; i++)
#pragma unroll
        for (int j = 0; j < 4; j++) acc[i][j] = 0.f;
    float lp0 = 0.f, lp1 = 0.f;

    const int NT = (NTOK / NSPLIT) / KT2;   // 64
    for (int t = 0; t < NT; t++) {
        CP_WAIT0();
        __syncthreads();
        if (t + 1 < NT) { prefetch(kglob0 + (t + 1) * KT2, (t + 1) & 1); CP_COMMIT(); }

        const uint32_t ksa = kbase(t & 1);
        const uint32_t vsa = ksa + KT2 * DP * 2;

        float S[4][4];
#pragma unroll
        for (int j = 0; j < 4; j++)
#pragma unroll
            for (int i = 0; i < 4; i++) S[j][i] = -C2OFF;

#pragma unroll
        for (int d0 = 0; d0 < 16; d0++) {
#pragma unroll
            for (int j = 0; j < 4; j += 2) {
                uint32_t bk4[4];
                ldsm_x4(bk4, ksa + (uint32_t)((j * 8 + krow) * DP + d0 * 16 + kcol) * 2);
                mma16816bf(S[j],     qf[d0], bk4[0], bk4[1]);
                mma16816bf(S[j + 1], qf[d0], bk4[2], bk4[3]);
            }
        }

        uint32_t Pa[2][4];
#pragma unroll
        for (int j = 0; j < 4; j++) {
            uint32_t p01 = ex2_f16x2(pack_f16(S[j][1], S[j][0]));
            uint32_t p23 = ex2_f16x2(pack_f16(S[j][3], S[j][2]));
            int kk = j >> 1;
            if ((j & 1) == 0) { Pa[kk][0] = p01; Pa[kk][1] = p23; }
            else              { Pa[kk][2] = p01; Pa[kk][3] = p23; }
        }

        // row sums on FMA pipe: regs 0,2 are row r0; regs 1,3 are row r1
        {
            __half2 h0 = __hadd2(__hadd2(*reinterpret_cast<__half2*>(&Pa[0][0]),
                                         *reinterpret_cast<__half2*>(&Pa[0][2])),
                                 __hadd2(*reinterpret_cast<__half2*>(&Pa[1][0]),
                                         *reinterpret_cast<__half2*>(&Pa[1][2])));
            __half2 h1 = __hadd2(__hadd2(*reinterpret_cast<__half2*>(&Pa[0][1]),
                                         *reinterpret_cast<__half2*>(&Pa[0][3])),
                                 __hadd2(*reinterpret_cast<__half2*>(&Pa[1][1]),
                                         *reinterpret_cast<__half2*>(&Pa[1][3])));
            float2 f0 = __half22float2(h0);
            float2 f1 = __half22float2(h1);
            lp0 += f0.x + f0.y;
            lp1 += f1.x + f1.y;
        }

#pragma unroll
        for (int dt = 0; dt < 32; dt += 2) {
#pragma unroll
            for (int kk = 0; kk < 2; kk++) {
                uint32_t bv4[4];
                ldsm_x4_t(bv4, vsa + (uint32_t)((kk * 16 + vrow) * DP + dt * 8 + vcol) * 2);
                mma16816h(acc[dt],     Pa[kk], bv4[0], bv4[1]);
                mma16816h(acc[dt + 1], Pa[kk], bv4[2], bv4[3]);
            }
        }
    }

    // quad reduction: lanes lk=0..3 hold partial sums of the same rows
    lp0 += __shfl_xor_sync(0xffffffffu, lp0, 1);
    lp0 += __shfl_xor_sync(0xffffffffu, lp0, 2);
    lp1 += __shfl_xor_sync(0xffffffffu, lp1, 1);
    lp1 += __shfl_xor_sync(0xffffffffu, lp1, 2);

    float* Ob = g_Osp + ((size_t)split * BATCH + b) * NTOK * DH;
    const int r0 = q0 + warp * 16 + (lane >> 2);
    const int r1 = r0 + 8;
    const int dcol = (lane & 3) * 2;
#pragma unroll
    for (int dt = 0; dt < 32; dt++) {
        int d = dt * 8 + dcol;
        *reinterpret_cast<float2*>(Ob + (size_t)r0 * DH + d) =
            make_float2(acc[dt][0], acc[dt][1]);
        *reinterpret_cast<float2*>(Ob + (size_t)r1 * DH + d) =
            make_float2(acc[dt][2], acc[dt][3]);
    }
    if ((lane & 3) == 0) {
        g_L[((size_t)split * BATCH + b) * NTOK + r0] = lp0;
        g_L[((size_t)split * BATCH + b) * NTOK + r1] = lp1;
    }
}

// ===========================================================================
// Kernel 4: output projection + residual, merge fused.
//   CTA 128c x 64n, grid 256, 8 warps (4c x 2n), warp tile 32c x 32n.
// ===========================================================================
__global__ void __launch_bounds__(256) oproj_kernel(
    const float* __restrict__ Wo, const float* __restrict__ bo,
    const float* __restrict__ F, float* __restrict__ out)
{
    extern __shared__ __align__(16) float dyn[];
    __shared__ float invs[64];

    const int b  = blockIdx.z;
    const int n0 = blockIdx.x * 64;
    const int c0 = blockIdx.y * 128;
    const int tid = threadIdx.x, warp = tid >> 5, lane = tid & 31;
    const int warp_c = warp & 3, warp_n = warp >> 2;
    const int g = lane >> 2, lk = lane & 3;

    float* Asp = dyn;                  // [2][128][36]
    float* Bsp = dyn + 2 * 128 * 36;   // [2][2][64][36]
    const uint32_t as_b = (uint32_t)__cvta_generic_to_shared(Asp);
    const uint32_t bs_b = (uint32_t)__cvta_generic_to_shared(Bsp);

    if (tid < 64) {
        int row = b * NTOK + n0 + tid;
        invs[tid] = 1.f / (g_L[row] + g_L[(size_t)BATCH * NTOK + row]);
    }

    float acc[2][4][4];
#pragma unroll
    for (int mb = 0; mb < 2; mb++)
#pragma unroll
        for (int ob = 0; ob < 4; ob++)
#pragma unroll
            for (int i = 0; i < 4; i++) acc[mb][ob][i] = 0.f;

    const float* O0 = g_Osp + (size_t)b * NTOK * DH;
    const float* O1 = g_Osp + ((size_t)BATCH + b) * NTOK * DH;

    auto stage_in = [&](int kt, int s) {
        int o0k = kt * 32;
#pragma unroll
        for (int p = 0; p < 4; p++) {
            int idx = tid + p * 256;
            int cc = idx >> 3, ch = (idx & 7) * 4;
            cp_async16(as_b + (uint32_t)((s * 128 + cc) * 36 + ch) * 4,
                       &Wo[(size_t)(c0 + cc) * DH + o0k + ch]);
        }
#pragma unroll
        for (int p = 0; p < 2; p++) {
            int idx = tid + p * 256;
            int nn = idx >> 3, ch = (idx & 7) * 4;
            size_t go = (size_t)(n0 + nn) * DH + o0k + ch;
            uint32_t so = (uint32_t)(((s * 2 + 0) * 64 + nn) * 36 + ch) * 4;
            cp_async16(bs_b + so, O0 + go);
            cp_async16(bs_b + so + 64 * 36 * 4, O1 + go);
        }
    };

    stage_in(0, 0);
    CP_COMMIT();

    for (int kt = 0; kt < 8; kt++) {
        CP_WAIT0();
        __syncthreads();
        if (kt + 1 < 8) { stage_in(kt + 1, (kt + 1) & 1); CP_COMMIT(); }
        const int s = kt & 1;

#pragma unroll
        for (int k8 = 0; k8 < 4; k8++) {
            const int kb = k8 * 8;
            uint32_t a[2][4];
#pragma unroll
            for (int mb = 0; mb < 2; mb++) {
                int rm = warp_c * 32 + mb * 16 + g;
                a[mb][0] = f2tf32(Asp[(s * 128 + rm) * 36 + kb + lk]);
                a[mb][1] = f2tf32(Asp[(s * 128 + rm + 8) * 36 + kb + lk]);
                a[mb][2] = f2tf32(Asp[(s * 128 + rm) * 36 + kb + 4 + lk]);
                a[mb][3] = f2tf32(Asp[(s * 128 + rm + 8) * 36 + kb + 4 + lk]);
            }
#pragma unroll
            for (int ob = 0; ob < 4; ob++) {
                int nc = warp_n * 32 + ob * 8 + g;
                float inv = invs[nc];
                float s0 = Bsp[((s * 2 + 0) * 64 + nc) * 36 + kb + lk]
                         + Bsp[((s * 2 + 1) * 64 + nc) * 36 + kb + lk];
                float s1 = Bsp[((s * 2 + 0) * 64 + nc) * 36 + kb + 4 + lk]
                         + Bsp[((s * 2 + 1) * 64 + nc) * 36 + kb + 4 + lk];
                uint32_t b0 = f2tf32(s0 * inv);
                uint32_t b1 = f2tf32(s1 * inv);
                mma_tf32(acc[0][ob], a[0], b0, b1);
                mma_tf32(acc[1][ob], a[1], b0, b1);
            }
        }
        __syncthreads();
    }

#pragma unroll
    for (int mb = 0; mb < 2; mb++) {
#pragma unroll
        for (int rr = 0; rr < 2; rr++) {
            int c = c0 + warp_c * 32 + mb * 16 + g + rr * 8;
            float bias = bo[c];
#pragma unroll
            for (int ob = 0; ob < 4; ob++) {
                int n = n0 + warp_n * 32 + ob * 8 + 2 * lk;
                size_t base = ((size_t)b * DH + c) * NTOK + n;
                float2 f = *reinterpret_cast<const float2*>(F + base);
                float2 r;
                r.x = f.x + bias + acc[mb][ob][rr * 2 + 0];
                r.y = f.y + bias + acc[mb][ob][rr * 2 + 1];
                *reinterpret_cast<float2*>(out + base) = r;
            }
        }
    }
}

// ===========================================================================
// Launch
// ===========================================================================
extern "C" void kernel_launch(void* const* d_in, const int* in_sizes, int n_in,
                              void* d_out, int out_size)
{
    const float* F  = (const float*)d_in[0];
    const float* FK = (const float*)d_in[1];
    const float* Wq = (const float*)d_in[2];
    const float* bq = (const float*)d_in[3];
    const float* Wk = (const float*)d_in[4];
    const float* bk = (const float*)d_in[5];
    const float* Wv = (const float*)d_in[6];
    const float* bv = (const float*)d_in[7];
    const float* Wo = (const float*)d_in[8];
    const float* bo = (const float*)d_in[9];
    float* out = (float*)d_out;

    const int qkv_smem   = (2 * 32 * 72 + 2 * 128 * 36) * 4;         // 55,296
    const int attn_smem  = (QT + 2 * 2 * KT2) * DP * 2;              // 101,376
    const int oproj_smem = (2 * 128 * 36 + 2 * 2 * 64 * 36) * 4;     // 73,728

    cudaFuncSetAttribute(qkvproj_kernel, cudaFuncAttributeMaxDynamicSharedMemorySize, qkv_smem);
    cudaFuncSetAttribute(attn_kernel,    cudaFuncAttributeMaxDynamicSharedMemorySize, attn_smem);
    cudaFuncSetAttribute(oproj_kernel,   cudaFuncAttributeMaxDynamicSharedMemorySize, oproj_smem);

    qkvproj_kernel<<<512, 256, qkv_smem>>>(F, FK, Wq, bq, Wk, bk, Wv, bv);
    attn_kernel<<<dim3(NTOK / QT, BATCH, NSPLIT), 128, attn_smem>>>();
    oproj_kernel<<<dim3(NTOK / 64, DH / 128, BATCH), 256, oproj_smem>>>(Wo, bo, F, out);
}

// round 12
// speedup vs baseline: 1.0659x; 1.0126x over previous
#include <cuda_runtime.h>
#include <cuda_bf16.h>
#include <cuda_fp16.h>
#include <cstdint>

// ---------------------------------------------------------------------------
// Problem constants
// ---------------------------------------------------------------------------
#define BATCH   2
#define NTOK    4096
#define DH      256
#define DK      32
#define SCALE   0.125f
#define LOG2E   1.4426950408889634f
#define QSCALE  (SCALE * LOG2E)
#define C2OFF   12.0f

// attention tiling
#define QT      64
#define KT2     32
#define DP      264
#define NSPLIT  2

// ---------------------------------------------------------------------------
// Scratch
// ---------------------------------------------------------------------------
__device__ __nv_bfloat16 g_Q[(size_t)BATCH * NTOK * DH];
__device__ __nv_bfloat16 g_K[(size_t)BATCH * NTOK * DH];
__device__ __half        g_V[(size_t)BATCH * NTOK * DH];
__device__ float         g_Osp[(size_t)NSPLIT * BATCH * NTOK * DH];
__device__ float         g_L[(size_t)NSPLIT * BATCH * NTOK];

// ---------------------------------------------------------------------------
// PTX helpers
// ---------------------------------------------------------------------------
__device__ __forceinline__ void mma16816bf(float* c, const uint32_t* a, uint32_t b0, uint32_t b1) {
    asm volatile(
        "mma.sync.aligned.m16n8k16.row.col.f32.bf16.bf16.f32 "
        "{%0,%1,%2,%3}, {%4,%5,%6,%7}, {%8,%9}, {%0,%1,%2,%3};\n"
        : "+f"(c[0]), "+f"(c[1]), "+f"(c[2]), "+f"(c[3])
        : "r"(a[0]), "r"(a[1]), "r"(a[2]), "r"(a[3]), "r"(b0), "r"(b1));
}

__device__ __forceinline__ void mma16816h(float* c, const uint32_t* a, uint32_t b0, uint32_t b1) {
    asm volatile(
        "mma.sync.aligned.m16n8k16.row.col.f32.f16.f16.f32 "
        "{%0,%1,%2,%3}, {%4,%5,%6,%7}, {%8,%9}, {%0,%1,%2,%3};\n"
        : "+f"(c[0]), "+f"(c[1]), "+f"(c[2]), "+f"(c[3])
        : "r"(a[0]), "r"(a[1]), "r"(a[2]), "r"(a[3]), "r"(b0), "r"(b1));
}

__device__ __forceinline__ void mma_tf32(float* c, const uint32_t* a, uint32_t b0, uint32_t b1) {
    asm volatile(
        "mma.sync.aligned.m16n8k8.row.col.f32.tf32.tf32.f32 "
        "{%0,%1,%2,%3}, {%4,%5,%6,%7}, {%8,%9}, {%0,%1,%2,%3};\n"
        : "+f"(c[0]), "+f"(c[1]), "+f"(c[2]), "+f"(c[3])
        : "r"(a[0]), "r"(a[1]), "r"(a[2]), "r"(a[3]), "r"(b0), "r"(b1));
}

__device__ __forceinline__ void ldsm_x4(uint32_t* r, uint32_t addr) {
    asm volatile("ldmatrix.sync.aligned.m8n8.x4.shared.b16 {%0,%1,%2,%3}, [%4];"
                 : "=r"(r[0]), "=r"(r[1]), "=r"(r[2]), "=r"(r[3]) : "r"(addr));
}

__device__ __forceinline__ void ldsm_x4_t(uint32_t* r, uint32_t addr) {
    asm volatile("ldmatrix.sync.aligned.m8n8.x4.trans.shared.b16 {%0,%1,%2,%3}, [%4];"
                 : "=r"(r[0]), "=r"(r[1]), "=r"(r[2]), "=r"(r[3]) : "r"(addr));
}

__device__ __forceinline__ uint32_t pack_f16(float hi, float lo) {
    uint32_t d;
    asm("cvt.rn.f16x2.f32 %0, %1, %2;" : "=r"(d) : "f"(hi), "f"(lo));
    return d;
}
__device__ __forceinline__ uint32_t ex2_f16x2(uint32_t s) {
    uint32_t d;
    asm("ex2.approx.f16x2 %0, %1;" : "=r"(d) : "r"(s));
    return d;
}

__device__ __forceinline__ void cp_async16(uint32_t smem, const void* gptr) {
    asm volatile("cp.async.cg.shared.global [%0], [%1], 16;" :: "r"(smem), "l"(gptr));
}
#define CP_COMMIT() asm volatile("cp.async.commit_group;")
#define CP_WAIT0()  asm volatile("cp.async.wait_group 0;")

// fast tf32: reinterpret f32 bits (RZ truncation in the tensor core)
#define FTF32(x) __float_as_uint(x)

// ===========================================================================
// Kernel 1: fused Q/K/V projections.
//   blocks [0, 256): Q projection, CTA 64n x 128o, warp tile 32x32,
//                    32-wide k stages. Fast-tf32 fragments (no cvt).
//   blocks [256, 512): K (bf16) / V (f16) projection, weights in registers.
// ===========================================================================
__global__ void __launch_bounds__(256) qkvproj_kernel(
    const float* __restrict__ F,  const float* __restrict__ FK,
    const float* __restrict__ Wq, const float* __restrict__ bq,
    const float* __restrict__ Wk, const float* __restrict__ bk,
    const float* __restrict__ Wv, const float* __restrict__ bv)
{
    extern __shared__ __align__(16) float dyn[];
    const int bid = blockIdx.x;
    const int tid = threadIdx.x;

    if (bid < 256) {
        // ----- Q projection -----
        const int n0 = (bid & 63) * 64;
        const int o0 = ((bid >> 6) & 1) * 128;
        const int b  = bid >> 7;
        const int warp = tid >> 5, lane = tid & 31;
        const int warp_n = warp & 1, warp_o = warp >> 1;   // 2n x 4o
        const int g = lane >> 2, lk = lane & 3;

        float* Asp = dyn;                 // [2][32][72]
        float* Wsp = dyn + 2 * 32 * 72;   // [2][128][36]
        const uint32_t as_b = (uint32_t)__cvta_generic_to_shared(Asp);
        const uint32_t ws_b = (uint32_t)__cvta_generic_to_shared(Wsp);

        float acc[2][4][4];
#pragma unroll
        for (int mb = 0; mb < 2; mb++)
#pragma unroll
            for (int ob = 0; ob < 4; ob++)
#pragma unroll
                for (int i = 0; i < 4; i++) acc[mb][ob][i] = 0.f;

        const float* Fb = F + (size_t)b * DH * NTOK;

        auto stage_in = [&](int kt, int s) {
            int c0 = kt * 32;
#pragma unroll
            for (int p = 0; p < 2; p++) {
                int idx = tid + p * 256;
                int cc = idx >> 4, ch = (idx & 15) * 4;
                cp_async16(as_b + (uint32_t)((s * 32 + cc) * 72 + ch) * 4,
                           &Fb[(size_t)(c0 + cc) * NTOK + n0 + ch]);
            }
#pragma unroll
            for (int p = 0; p < 4; p++) {
                int idx = tid + p * 256;
                int oo = idx >> 3, ch = (idx & 7) * 4;
                cp_async16(ws_b + (uint32_t)((s * 128 + oo) * 36 + ch) * 4,
                           &Wq[(size_t)(o0 + oo) * DH + c0 + ch]);
            }
        };

        stage_in(0, 0);
        CP_COMMIT();

        for (int kt = 0; kt < 8; kt++) {
            CP_WAIT0();
            __syncthreads();
            if (kt + 1 < 8) { stage_in(kt + 1, (kt + 1) & 1); CP_COMMIT(); }
            const int s = kt & 1;

#pragma unroll
            for (int k8 = 0; k8 < 4; k8++) {
                const int kb = k8 * 8;
                uint32_t a[2][4];
#pragma unroll
                for (int mb = 0; mb < 2; mb++) {
                    int rm = warp_n * 32 + mb * 16 + g;
                    a[mb][0] = FTF32(Asp[(s * 32 + kb + lk) * 72 + rm]);
                    a[mb][1] = FTF32(Asp[(s * 32 + kb + lk) * 72 + rm + 8]);
                    a[mb][2] = FTF32(Asp[(s * 32 + kb + 4 + lk) * 72 + rm]);
                    a[mb][3] = FTF32(Asp[(s * 32 + kb + 4 + lk) * 72 + rm + 8]);
                }
#pragma unroll
                for (int ob = 0; ob < 4; ob++) {
                    int oc = warp_o * 32 + ob * 8 + g;
                    uint32_t b0 = FTF32(Wsp[(s * 128 + oc) * 36 + kb + lk]);
                    uint32_t b1 = FTF32(Wsp[(s * 128 + oc) * 36 + kb + 4 + lk]);
                    mma_tf32(acc[0][ob], a[0], b0, b1);
                    mma_tf32(acc[1][ob], a[1], b0, b1);
                }
            }
            __syncthreads();
        }

#pragma unroll
        for (int ob = 0; ob < 4; ob++) {
            int o = o0 + warp_o * 32 + ob * 8 + 2 * lk;
            float bv0 = bq[o], bv1 = bq[o + 1];
#pragma unroll
            for (int mb = 0; mb < 2; mb++) {
                int r = n0 + warp_n * 32 + mb * 16 + g;
                __nv_bfloat162 lo = __floats2bfloat162_rn(
                    (acc[mb][ob][0] + bv0) * QSCALE, (acc[mb][ob][1] + bv1) * QSCALE);
                __nv_bfloat162 hi = __floats2bfloat162_rn(
                    (acc[mb][ob][2] + bv0) * QSCALE, (acc[mb][ob][3] + bv1) * QSCALE);
                *reinterpret_cast<uint32_t*>(&g_Q[((size_t)b * NTOK + r) * DH + o]) =
                    *reinterpret_cast<uint32_t*>(&lo);
                *reinterpret_cast<uint32_t*>(&g_Q[((size_t)b * NTOK + r + 8) * DH + o]) =
                    *reinterpret_cast<uint32_t*>(&hi);
            }
        }
    } else {
        // ----- K / V projection -----
        const int bid2 = bid - 256;
        const bool isK = (bid2 < 128);
        const float* W    = isK ? Wk : Wv;
        const float* bias = isK ? bk : bv;

        const int t0 = (bid2 & 127) * 64;
        const int b  = t0 >> 12;
        const int n0 = t0 & (NTOK - 1);
        const int o  = tid;

        float* xs = dyn;   // [64][36]

        float w[32];
#pragma unroll
        for (int i = 0; i < 8; i++) {
            float4 v = *reinterpret_cast<const float4*>(&W[(size_t)o * DK + i * 4]);
            w[i * 4 + 0] = v.x; w[i * 4 + 1] = v.y; w[i * 4 + 2] = v.z; w[i * 4 + 3] = v.w;
        }
        const float bb = bias[o];

        const float* FKb = FK + (size_t)b * DK * NTOK;
#pragma unroll
        for (int p = 0; p < 2; p++) {
            int idx = tid + p * 256;
            int c = idx >> 4, t4 = (idx & 15) * 4;
            float4 v = *reinterpret_cast<const float4*>(&FKb[(size_t)c * NTOK + n0 + t4]);
            xs[(t4 + 0) * 36 + c] = v.x; xs[(t4 + 1) * 36 + c] = v.y;
            xs[(t4 + 2) * 36 + c] = v.z; xs[(t4 + 3) * 36 + c] = v.w;
        }
        __syncthreads();

        for (int tok = 0; tok < 64; tok++) {
            float acc = bb;
#pragma unroll
            for (int i = 0; i < 8; i++) {
                float4 x = *reinterpret_cast<float4*>(&xs[tok * 36 + i * 4]);
                acc += x.x * w[i * 4 + 0] + x.y * w[i * 4 + 1]
                     + x.z * w[i * 4 + 2] + x.w * w[i * 4 + 3];
            }
            size_t di = ((size_t)b * NTOK + n0 + tok) * DH + o;
            if (isK) g_K[di] = __float2bfloat16(acc);
            else     g_V[di] = __float2half(acc);
        }
    }
}

// ===========================================================================
// Kernel 3: flash attention, split-KV, Q fragments register-resident.
//   (frozen)
// ===========================================================================
__global__ void __launch_bounds__(128) attn_kernel()
{
    extern __shared__ __align__(16) __nv_bfloat16 sm[];
    __nv_bfloat16* Qs = sm;

    const int b     = blockIdx.y;
    const int split = blockIdx.z;
    const int q0    = blockIdx.x * QT;
    const int tid = threadIdx.x, warp = tid >> 5, lane = tid & 31;

    const int kglob0 = split * (NTOK / NSPLIT);

    const __nv_bfloat16* Qg = g_Q + ((size_t)b * NTOK + q0) * DH;
    const __nv_bfloat16* Kg = g_K + (size_t)b * NTOK * DH;
    const __half*        Vg = g_V + (size_t)b * NTOK * DH;

    const uint32_t smb = (uint32_t)__cvta_generic_to_shared(sm);

    const int qrow = warp * 16 + (lane & 15);
    const int qcol = (lane >> 4) * 8;
    const uint32_t qaddr = smb + (uint32_t)(qrow * DP + qcol) * 2;
    const int krow = (lane & 7) + ((lane >> 4) << 3);
    const int kcol = ((lane >> 3) & 1) * 8;
    const int vrow = lane & 15;
    const int vcol = (lane >> 4) * 8;

    auto kbase = [&](int s) -> uint32_t { return smb + (uint32_t)(QT + s * 2 * KT2) * DP * 2; };

    auto prefetch = [&](int k0, int s) {
        uint32_t kb = kbase(s);
        uint32_t vb = kb + KT2 * DP * 2;
#pragma unroll
        for (int i = 0; i < 8; i++) {
            int idx = tid + i * 128;
            int r = idx >> 5, c = (idx & 31) * 8;
            uint32_t so = (uint32_t)(r * DP + c) * 2;
            cp_async16(kb + so, Kg + (size_t)(k0 + r) * DH + c);
            cp_async16(vb + so, Vg + (size_t)(k0 + r) * DH + c);
        }
    };

    prefetch(kglob0, 0);
    CP_COMMIT();

    for (int idx = tid; idx < QT * 32; idx += 128) {
        int r = idx >> 5, c = (idx & 31) * 8;
        *reinterpret_cast<uint4*>(Qs + r * DP + c) =
            *reinterpret_cast<const uint4*>(Qg + (size_t)r * DH + c);
    }
    __syncthreads();

    uint32_t qf[16][4];
#pragma unroll
    for (int d0 = 0; d0 < 16; d0++)
        ldsm_x4(qf[d0], qaddr + (uint32_t)(d0 * 16) * 2);

    float acc[32][4];
#pragma unroll
    for (int i = 0; i < 32; i++)
#pragma unroll
        for (int j = 0; j < 4; j++) acc[i][j] = 0.f;
    float lp0 = 0.f, lp1 = 0.f;

    const int NT = (NTOK / NSPLIT) / KT2;   // 64
    for (int t = 0; t < NT; t++) {
        CP_WAIT0();
        __syncthreads();
        if (t + 1 < NT) { prefetch(kglob0 + (t + 1) * KT2, (t + 1) & 1); CP_COMMIT(); }

        const uint32_t ksa = kbase(t & 1);
        const uint32_t vsa = ksa + KT2 * DP * 2;

        float S[4][4];
#pragma unroll
        for (int j = 0; j < 4; j++)
#pragma unroll
            for (int i = 0; i < 4; i++) S[j][i] = -C2OFF;

#pragma unroll
        for (int d0 = 0; d0 < 16; d0++) {
#pragma unroll
            for (int j = 0; j < 4; j += 2) {
                uint32_t bk4[4];
                ldsm_x4(bk4, ksa + (uint32_t)((j * 8 + krow) * DP + d0 * 16 + kcol) * 2);
                mma16816bf(S[j],     qf[d0], bk4[0], bk4[1]);
                mma16816bf(S[j + 1], qf[d0], bk4[2], bk4[3]);
            }
        }

        uint32_t Pa[2][4];
#pragma unroll
        for (int j = 0; j < 4; j++) {
            uint32_t p01 = ex2_f16x2(pack_f16(S[j][1], S[j][0]));
            uint32_t p23 = ex2_f16x2(pack_f16(S[j][3], S[j][2]));
            int kk = j >> 1;
            if ((j & 1) == 0) { Pa[kk][0] = p01; Pa[kk][1] = p23; }
            else              { Pa[kk][2] = p01; Pa[kk][3] = p23; }
        }

        // row sums on FMA pipe
        {
            __half2 h0 = __hadd2(__hadd2(*reinterpret_cast<__half2*>(&Pa[0][0]),
                                         *reinterpret_cast<__half2*>(&Pa[0][2])),
                                 __hadd2(*reinterpret_cast<__half2*>(&Pa[1][0]),
                                         *reinterpret_cast<__half2*>(&Pa[1][2])));
            __half2 h1 = __hadd2(__hadd2(*reinterpret_cast<__half2*>(&Pa[0][1]),
                                         *reinterpret_cast<__half2*>(&Pa[0][3])),
                                 __hadd2(*reinterpret_cast<__half2*>(&Pa[1][1]),
                                         *reinterpret_cast<__half2*>(&Pa[1][3])));
            float2 f0 = __half22float2(h0);
            float2 f1 = __half22float2(h1);
            lp0 += f0.x + f0.y;
            lp1 += f1.x + f1.y;
        }

#pragma unroll
        for (int dt = 0; dt < 32; dt += 2) {
#pragma unroll
            for (int kk = 0; kk < 2; kk++) {
                uint32_t bv4[4];
                ldsm_x4_t(bv4, vsa + (uint32_t)((kk * 16 + vrow) * DP + dt * 8 + vcol) * 2);
                mma16816h(acc[dt],     Pa[kk], bv4[0], bv4[1]);
                mma16816h(acc[dt + 1], Pa[kk], bv4[2], bv4[3]);
            }
        }
    }

    lp0 += __shfl_xor_sync(0xffffffffu, lp0, 1);
    lp0 += __shfl_xor_sync(0xffffffffu, lp0, 2);
    lp1 += __shfl_xor_sync(0xffffffffu, lp1, 1);
    lp1 += __shfl_xor_sync(0xffffffffu, lp1, 2);

    float* Ob = g_Osp + ((size_t)split * BATCH + b) * NTOK * DH;
    const int r0 = q0 + warp * 16 + (lane >> 2);
    const int r1 = r0 + 8;
    const int dcol = (lane & 3) * 2;
#pragma unroll
    for (int dt = 0; dt < 32; dt++) {
        int d = dt * 8 + dcol;
        *reinterpret_cast<float2*>(Ob + (size_t)r0 * DH + d) =
            make_float2(acc[dt][0], acc[dt][1]);
        *reinterpret_cast<float2*>(Ob + (size_t)r1 * DH + d) =
            make_float2(acc[dt][2], acc[dt][3]);
    }
    if ((lane & 3) == 0) {
        g_L[((size_t)split * BATCH + b) * NTOK + r0] = lp0;
        g_L[((size_t)split * BATCH + b) * NTOK + r1] = lp1;
    }
}

// ===========================================================================
// Kernel 4: output projection + residual, merge fused.
//   CTA 128c x 64n, grid 256, warp tile 32c x 32n.
//   Splits pre-merged + normalized in smem once per stage; B-fragment = 1 LDS.
//   Fast-tf32 fragments (no cvt).
// ===========================================================================
__global__ void __launch_bounds__(256) oproj_kernel(
    const float* __restrict__ Wo, const float* __restrict__ bo,
    const float* __restrict__ F, float* __restrict__ out)
{
    extern __shared__ __align__(16) float dyn[];
    __shared__ float invs[64];

    const int b  = blockIdx.z;
    const int n0 = blockIdx.x * 64;
    const int c0 = blockIdx.y * 128;
    const int tid = threadIdx.x, warp = tid >> 5, lane = tid & 31;
    const int warp_c = warp & 3, warp_n = warp >> 2;
    const int g = lane >> 2, lk = lane & 3;

    float* Asp = dyn;                  // [2][128][36]
    float* Bsp = dyn + 2 * 128 * 36;   // [2][2][64][36]
    const uint32_t as_b = (uint32_t)__cvta_generic_to_shared(Asp);
    const uint32_t bs_b = (uint32_t)__cvta_generic_to_shared(Bsp);

    if (tid < 64) {
        int row = b * NTOK + n0 + tid;
        invs[tid] = 1.f / (g_L[row] + g_L[(size_t)BATCH * NTOK + row]);
    }

    float acc[2][4][4];
#pragma unroll
    for (int mb = 0; mb < 2; mb++)
#pragma unroll
        for (int ob = 0; ob < 4; ob++)
#pragma unroll
            for (int i = 0; i < 4; i++) acc[mb][ob][i] = 0.f;

    const float* O0 = g_Osp + (size_t)b * NTOK * DH;
    const float* O1 = g_Osp + ((size_t)BATCH + b) * NTOK * DH;

    auto stage_in = [&](int kt, int s) {
        int o0k = kt * 32;
#pragma unroll
        for (int p = 0; p < 4; p++) {
            int idx = tid + p * 256;
            int cc = idx >> 3, ch = (idx & 7) * 4;
            cp_async16(as_b + (uint32_t)((s * 128 + cc) * 36 + ch) * 4,
                       &Wo[(size_t)(c0 + cc) * DH + o0k + ch]);
        }
#pragma unroll
        for (int p = 0; p < 2; p++) {
            int idx = tid + p * 256;
            int nn = idx >> 3, ch = (idx & 7) * 4;
            size_t go = (size_t)(n0 + nn) * DH + o0k + ch;
            uint32_t so = (uint32_t)(((s * 2 + 0) * 64 + nn) * 36 + ch) * 4;
            cp_async16(bs_b + so, O0 + go);
            cp_async16(bs_b + so + 64 * 36 * 4, O1 + go);
        }
    };

    stage_in(0, 0);
    CP_COMMIT();

    for (int kt = 0; kt < 8; kt++) {
        CP_WAIT0();
        __syncthreads();
        if (kt + 1 < 8) { stage_in(kt + 1, (kt + 1) & 1); CP_COMMIT(); }
        const int s = kt & 1;

        // pre-merge: Bs[s][0] = (Bs[s][0] + Bs[s][1]) * inv[n]   (in place)
#pragma unroll
        for (int p = 0; p < 2; p++) {
            int idx = tid + p * 256;
            int nn = idx >> 3, ch = (idx & 7) * 4;
            float inv = invs[nn];
            float* base0 = &Bsp[((s * 2 + 0) * 64 + nn) * 36 + ch];
            float4 x0 = *reinterpret_cast<float4*>(base0);
            float4 x1 = *reinterpret_cast<float4*>(base0 + 64 * 36);
            x0.x = (x0.x + x1.x) * inv;
            x0.y = (x0.y + x1.y) * inv;
            x0.z = (x0.z + x1.z) * inv;
            x0.w = (x0.w + x1.w) * inv;
            *reinterpret_cast<float4*>(base0) = x0;
        }
        __syncthreads();

#pragma unroll
        for (int k8 = 0; k8 < 4; k8++) {
            const int kb = k8 * 8;
            uint32_t a[2][4];
#pragma unroll
            for (int mb = 0; mb < 2; mb++) {
                int rm = warp_c * 32 + mb * 16 + g;
                a[mb][0] = FTF32(Asp[(s * 128 + rm) * 36 + kb + lk]);
                a[mb][1] = FTF32(Asp[(s * 128 + rm + 8) * 36 + kb + lk]);
                a[mb][2] = FTF32(Asp[(s * 128 + rm) * 36 + kb + 4 + lk]);
                a[mb][3] = FTF32(Asp[(s * 128 + rm + 8) * 36 + kb + 4 + lk]);
            }
#pragma unroll
            for (int ob = 0; ob < 4; ob++) {
                int nc = warp_n * 32 + ob * 8 + g;
                uint32_t b0 = FTF32(Bsp[((s * 2 + 0) * 64 + nc) * 36 + kb + lk]);
                uint32_t b1 = FTF32(Bsp[((s * 2 + 0) * 64 + nc) * 36 + kb + 4 + lk]);
                mma_tf32(acc[0][ob], a[0], b0, b1);
                mma_tf32(acc[1][ob], a[1], b0, b1);
            }
        }
        __syncthreads();
    }

#pragma unroll
    for (int mb = 0; mb < 2; mb++) {
#pragma unroll
        for (int rr = 0; rr < 2; rr++) {
            int c = c0 + warp_c * 32 + mb * 16 + g + rr * 8;
            float bias = bo[c];
#pragma unroll
            for (int ob = 0; ob < 4; ob++) {
                int n = n0 + warp_n * 32 + ob * 8 + 2 * lk;
                size_t base = ((size_t)b * DH + c) * NTOK + n;
                float2 f = *reinterpret_cast<const float2*>(F + base);
                float2 r;
                r.x = f.x + bias + acc[mb][ob][rr * 2 + 0];
                r.y = f.y + bias + acc[mb][ob][rr * 2 + 1];
                *reinterpret_cast<float2*>(out + base) = r;
            }
        }
    }
}

// ===========================================================================
// Launch
// ===========================================================================
extern "C" void kernel_launch(void* const* d_in, const int* in_sizes, int n_in,
                              void* d_out, int out_size)
{
    const float* F  = (const float*)d_in[0];
    const float* FK = (const float*)d_in[1];
    const float* Wq = (const float*)d_in[2];
    const float* bq = (const float*)d_in[3];
    const float* Wk = (const float*)d_in[4];
    const float* bk = (const float*)d_in[5];
    const float* Wv = (const float*)d_in[6];
    const float* bv = (const float*)d_in[7];
    const float* Wo = (const float*)d_in[8];
    const float* bo = (const float*)d_in[9];
    float* out = (float*)d_out;

    const int qkv_smem   = (2 * 32 * 72 + 2 * 128 * 36) * 4;         // 55,296
    const int attn_smem  = (QT + 2 * 2 * KT2) * DP * 2;              // 101,376
    const int oproj_smem = (2 * 128 * 36 + 2 * 2 * 64 * 36) * 4;     // 73,728

    cudaFuncSetAttribute(qkvproj_kernel, cudaFuncAttributeMaxDynamicSharedMemorySize, qkv_smem);
    cudaFuncSetAttribute(attn_kernel,    cudaFuncAttributeMaxDynamicSharedMemorySize, attn_smem);
    cudaFuncSetAttribute(oproj_kernel,   cudaFuncAttributeMaxDynamicSharedMemorySize, oproj_smem);

    qkvproj_kernel<<<512, 256, qkv_smem>>>(F, FK, Wq, bq, Wk, bk, Wv, bv);
    attn_kernel<<<dim3(NTOK / QT, BATCH, NSPLIT), 128, attn_smem>>>();
    oproj_kernel<<<dim3(NTOK / 64, DH / 128, BATCH), 256, oproj_smem>>>(Wo, bo, F, out);
}